// round 1
// baseline (speedup 1.0000x reference)
#include <cuda_runtime.h>
#include <math.h>

#define D_MODEL 1024
#define NH 16
#define HD 64
#define SEQL 2048
#define BATCH 4
#define MTOT (BATCH * SEQL)

// Scratch (static device globals — allocation-free per harness rules)
__device__ float g_q[(size_t)BATCH * NH * SEQL * HD];
__device__ float g_k[(size_t)BATCH * NH * SEQL * HD];
__device__ float g_v[(size_t)BATCH * NH * SEQL * HD];
__device__ float g_attn[(size_t)MTOT * D_MODEL];

// ---------------------------------------------------------------------------
// Tiled SGEMM: out[m, n] = sum_j A[m, j] * W[n, j]   (i.e. A @ W^T)
// BM=BN=128, BK=16, 256 threads, 8x8 per thread.
// mode 0: q (RoPE, write [b,h,s,d])   mode 1: k (RoPE, [b,h,s,d])
// mode 2: v (no RoPE, [b,h,s,d])      mode 3: plain row-major write (proj)
// ---------------------------------------------------------------------------
__global__ __launch_bounds__(256) void gemm_kernel(
    const float* __restrict__ A,
    const float* __restrict__ W0, const float* __restrict__ W1,
    const float* __restrict__ W2,
    float* __restrict__ D0, float* __restrict__ D1, float* __restrict__ D2,
    const int* __restrict__ tp, int mode_base)
{
    __shared__ float As[16][132];
    __shared__ float Bs[16][132];

    int mode = mode_base + blockIdx.z;
    const float* W = (mode == 1) ? W1 : (mode == 2) ? W2 : W0;
    float* Dst     = (mode == 1) ? D1 : (mode == 2) ? D2 : D0;

    int tid = threadIdx.x;
    int tx = tid & 15, ty = tid >> 4;
    int m0 = blockIdx.y * 128;
    int n0 = blockIdx.x * 128;

    const float* Ap = A + (size_t)m0 * D_MODEL;
    const float* Wp = W + (size_t)n0 * D_MODEL;

    float acc[8][8];
#pragma unroll
    for (int i = 0; i < 8; i++)
#pragma unroll
        for (int j = 0; j < 8; j++) acc[i][j] = 0.f;

    for (int k0 = 0; k0 < D_MODEL; k0 += 16) {
        __syncthreads();
#pragma unroll
        for (int l = 0; l < 2; l++) {
            int idx = tid + l * 256;          // 0..511 float4 slots
            int r = idx >> 2;                 // 0..127 tile row
            int kc = (idx & 3) << 2;          // 0,4,8,12
            float4 av = *reinterpret_cast<const float4*>(
                Ap + (size_t)r * D_MODEL + k0 + kc);
            As[kc + 0][r] = av.x; As[kc + 1][r] = av.y;
            As[kc + 2][r] = av.z; As[kc + 3][r] = av.w;
            float4 bv = *reinterpret_cast<const float4*>(
                Wp + (size_t)r * D_MODEL + k0 + kc);
            Bs[kc + 0][r] = bv.x; Bs[kc + 1][r] = bv.y;
            Bs[kc + 2][r] = bv.z; Bs[kc + 3][r] = bv.w;
        }
        __syncthreads();
#pragma unroll
        for (int kk = 0; kk < 16; kk++) {
            float a[8], b[8];
#pragma unroll
            for (int i = 0; i < 8; i++) a[i] = As[kk][ty * 8 + i];
#pragma unroll
            for (int j = 0; j < 8; j++) b[j] = Bs[kk][tx * 8 + j];
#pragma unroll
            for (int i = 0; i < 8; i++)
#pragma unroll
                for (int j = 0; j < 8; j++)
                    acc[i][j] = fmaf(a[i], b[j], acc[i][j]);
        }
    }

    if (mode == 3) {
#pragma unroll
        for (int i = 0; i < 8; i++) {
            int m = m0 + ty * 8 + i;
#pragma unroll
            for (int j = 0; j < 8; j++)
                Dst[(size_t)m * D_MODEL + n0 + tx * 8 + j] = acc[i][j];
        }
        return;
    }

    // q/k/v epilogue: optional RoPE, write [b, h, s, d]
#pragma unroll
    for (int i = 0; i < 8; i++) {
        int m = m0 + ty * 8 + i;
        int b = m / SEQL, s = m % SEQL;
        float pos = (float)tp[s];
#pragma unroll
        for (int j = 0; j < 8; j += 2) {
            int c = n0 + tx * 8 + j;
            int h = c >> 6;
            int d = c & 63;
            float e0 = acc[i][j], e1 = acc[i][j + 1];
            float v0 = e0, v1 = e1;
            if (mode != 2) {
                int p = d >> 1;
                float theta = 1.f / powf(10000.f, (float)(2 * p) * (1.f / 64.f));
                float ang = pos * theta;
                float sn, cs;
                sincosf(ang, &sn, &cs);
                v0 = e0 * cs - e1 * sn;
                v1 = e0 * sn + e1 * cs;
            }
            size_t o = (((size_t)(b * NH + h)) * SEQL + s) * HD + d;
            Dst[o]     = v0;
            Dst[o + 1] = v1;
        }
    }
}

// ---------------------------------------------------------------------------
// Flash attention (fp32, online softmax).
// Block = (bh, q-tile of 64 rows). 256 threads, 4x4 register tiles.
// Smem: Qs/Ks/Vs/Ps each 64x65 floats (pad avoids bank conflicts) = 66560 B.
// ---------------------------------------------------------------------------
#define ATTN_SMEM (4 * 64 * 65 * (int)sizeof(float))

__global__ __launch_bounds__(256) void attn_kernel()
{
    extern __shared__ float sm[];
    float* Qs = sm;
    float* Ks = sm + 64 * 65;
    float* Vs = sm + 2 * 64 * 65;
    float* Ps = sm + 3 * 64 * 65;

    int bh = blockIdx.y;
    int qt = gridDim.x - 1 - blockIdx.x;  // big (late-causal) tiles first
    int tid = threadIdx.x;
    int tx = tid & 15, ty = tid >> 4;

    const float* qp = g_q + (size_t)bh * SEQL * HD + (size_t)qt * 64 * HD;
    const float* kp = g_k + (size_t)bh * SEQL * HD;
    const float* vp = g_v + (size_t)bh * SEQL * HD;

    // load Q tile (coalesced float4)
#pragma unroll
    for (int l = 0; l < 4; l++) {
        int idx4 = tid + l * 256;          // 0..1023
        int r = idx4 >> 4;                 // row
        int dc = (idx4 & 15) << 2;         // dim chunk
        float4 qv = *reinterpret_cast<const float4*>(qp + r * HD + dc);
        Qs[r * 65 + dc + 0] = qv.x; Qs[r * 65 + dc + 1] = qv.y;
        Qs[r * 65 + dc + 2] = qv.z; Qs[r * 65 + dc + 3] = qv.w;
    }

    float o[4][4];
    float mr[4], lr[4];
#pragma unroll
    for (int i = 0; i < 4; i++) {
        mr[i] = -1e30f; lr[i] = 0.f;
#pragma unroll
        for (int j = 0; j < 4; j++) o[i][j] = 0.f;
    }

    for (int t = 0; t <= qt; t++) {
        __syncthreads();
        const float* kt = kp + (size_t)t * 64 * HD;
        const float* vt = vp + (size_t)t * 64 * HD;
#pragma unroll
        for (int l = 0; l < 4; l++) {
            int idx4 = tid + l * 256;
            int r = idx4 >> 4;
            int dc = (idx4 & 15) << 2;
            float4 kv = *reinterpret_cast<const float4*>(kt + r * HD + dc);
            Ks[r * 65 + dc + 0] = kv.x; Ks[r * 65 + dc + 1] = kv.y;
            Ks[r * 65 + dc + 2] = kv.z; Ks[r * 65 + dc + 3] = kv.w;
            float4 vv = *reinterpret_cast<const float4*>(vt + r * HD + dc);
            Vs[r * 65 + dc + 0] = vv.x; Vs[r * 65 + dc + 1] = vv.y;
            Vs[r * 65 + dc + 2] = vv.z; Vs[r * 65 + dc + 3] = vv.w;
        }
        __syncthreads();

        // S = Q K^T (64x64x64), thread tile 4x4
        float sc[4][4];
#pragma unroll
        for (int i = 0; i < 4; i++)
#pragma unroll
            for (int j = 0; j < 4; j++) sc[i][j] = 0.f;

#pragma unroll 8
        for (int d = 0; d < HD; d++) {
            float qa[4], kb[4];
#pragma unroll
            for (int i = 0; i < 4; i++) qa[i] = Qs[(ty * 4 + i) * 65 + d];
#pragma unroll
            for (int j = 0; j < 4; j++) kb[j] = Ks[(tx * 4 + j) * 65 + d];
#pragma unroll
            for (int i = 0; i < 4; i++)
#pragma unroll
                for (int j = 0; j < 4; j++)
                    sc[i][j] = fmaf(qa[i], kb[j], sc[i][j]);
        }

        bool diag = (t == qt);
#pragma unroll
        for (int i = 0; i < 4; i++) {
            int r = ty * 4 + i;
#pragma unroll
            for (int j = 0; j < 4; j++) {
                int c = tx * 4 + j;
                sc[i][j] = (diag && c > r) ? -1e30f : sc[i][j] * 0.125f;
            }
        }

        // online softmax per row (rows split across 16 lanes with same ty;
        // those 16 lanes are a contiguous half-warp -> shfl_xor works)
#pragma unroll
        for (int i = 0; i < 4; i++) {
            float tm = fmaxf(fmaxf(sc[i][0], sc[i][1]),
                             fmaxf(sc[i][2], sc[i][3]));
#pragma unroll
            for (int off = 8; off > 0; off >>= 1)
                tm = fmaxf(tm, __shfl_xor_sync(0xffffffffu, tm, off));
            float mn = fmaxf(mr[i], tm);
            float corr = expf(mr[i] - mn);
            mr[i] = mn;
            float rs = 0.f;
#pragma unroll
            for (int j = 0; j < 4; j++) {
                sc[i][j] = expf(sc[i][j] - mn);
                rs += sc[i][j];
            }
#pragma unroll
            for (int off = 8; off > 0; off >>= 1)
                rs += __shfl_xor_sync(0xffffffffu, rs, off);
            lr[i] = lr[i] * corr + rs;
#pragma unroll
            for (int j = 0; j < 4; j++) {
                o[i][j] *= corr;
                Ps[(ty * 4 + i) * 65 + tx * 4 + j] = sc[i][j];
            }
        }
        __syncthreads();

        // O += P V (64x64x64)
#pragma unroll 8
        for (int c = 0; c < 64; c++) {
            float pa[4], vb[4];
#pragma unroll
            for (int i = 0; i < 4; i++) pa[i] = Ps[(ty * 4 + i) * 65 + c];
#pragma unroll
            for (int j = 0; j < 4; j++) vb[j] = Vs[c * 65 + tx * 4 + j];
#pragma unroll
            for (int i = 0; i < 4; i++)
#pragma unroll
                for (int j = 0; j < 4; j++)
                    o[i][j] = fmaf(pa[i], vb[j], o[i][j]);
        }
    }

    // write [b, s, h*64+d] layout for the output projection
    int b = bh >> 4, h = bh & 15;
#pragma unroll
    for (int i = 0; i < 4; i++) {
        float inv = 1.f / lr[i];
        int s = qt * 64 + ty * 4 + i;
        size_t base = ((size_t)b * SEQL + s) * D_MODEL + h * HD + tx * 4;
#pragma unroll
        for (int j = 0; j < 4; j++) g_attn[base + j] = o[i][j] * inv;
    }
}

// ---------------------------------------------------------------------------
extern "C" void kernel_launch(void* const* d_in, const int* in_sizes, int n_in,
                              void* d_out, int out_size)
{
    const float* x  = (const float*)d_in[0];
    const int*   tp = (const int*)d_in[1];
    const float* wq = (const float*)d_in[2];
    const float* wk = (const float*)d_in[3];
    const float* wv = (const float*)d_in[4];
    const float* wo = (const float*)d_in[5];
    float* out = (float*)d_out;

    float *qg, *kg, *vg, *ag;
    cudaGetSymbolAddress((void**)&qg, g_q);
    cudaGetSymbolAddress((void**)&kg, g_k);
    cudaGetSymbolAddress((void**)&vg, g_v);
    cudaGetSymbolAddress((void**)&ag, g_attn);

    cudaFuncSetAttribute(attn_kernel,
                         cudaFuncAttributeMaxDynamicSharedMemorySize,
                         ATTN_SMEM);

    // QKV (3 GEMMs fused into one launch via z) + RoPE epilogue
    dim3 gqkv(D_MODEL / 128, MTOT / 128, 3);
    gemm_kernel<<<gqkv, 256>>>(x, wq, wk, wv, qg, kg, vg, tp, 0);

    // causal flash attention
    dim3 gattn(SEQL / 64, BATCH * NH);
    attn_kernel<<<gattn, 256, ATTN_SMEM>>>();

    // output projection
    dim3 gproj(D_MODEL / 128, MTOT / 128, 1);
    gemm_kernel<<<gproj, 256>>>(ag, wo, nullptr, nullptr,
                                out, nullptr, nullptr, tp, 3);
}

// round 3
// speedup vs baseline: 1.4861x; 1.4861x over previous
#include <cuda_runtime.h>
#include <cuda_bf16.h>
#include <math.h>
#include <cstdint>

#define D_MODEL 1024
#define NH 16
#define HD 64
#define SEQL 2048
#define BATCH 4
#define MTOT (BATCH * SEQL)

// Scratch (static device globals — allocation-free per harness rules)
__device__ float g_q[(size_t)BATCH * NH * SEQL * HD];
__device__ float g_k[(size_t)BATCH * NH * SEQL * HD];
__device__ float g_v[(size_t)BATCH * NH * SEQL * HD];
__device__ float g_attn[(size_t)MTOT * D_MODEL];
__device__ float g_rcos[32 * SEQL];   // [p][s]
__device__ float g_rsin[32 * SEQL];

// ===========================================================================
// helpers
// ===========================================================================
__device__ __forceinline__ uint32_t smem_to_u32(const void* p) {
    uint32_t a;
    asm("{ .reg .u64 t; cvta.to.shared.u64 t, %1; cvt.u32.u64 %0, t; }"
        : "=r"(a) : "l"(p));
    return a;
}

__device__ __forceinline__ void ldm_x4(uint32_t* r, uint32_t addr) {
    asm volatile("ldmatrix.sync.aligned.m8n8.x4.shared.b16 {%0,%1,%2,%3}, [%4];"
                 : "=r"(r[0]), "=r"(r[1]), "=r"(r[2]), "=r"(r[3]) : "r"(addr));
}
__device__ __forceinline__ void ldm_x2(uint32_t* r, uint32_t addr) {
    asm volatile("ldmatrix.sync.aligned.m8n8.x2.shared.b16 {%0,%1}, [%2];"
                 : "=r"(r[0]), "=r"(r[1]) : "r"(addr));
}

__device__ __forceinline__ void mma_bf16(float* c, const uint32_t* a,
                                         const uint32_t* b) {
    asm volatile(
        "mma.sync.aligned.m16n8k16.row.col.f32.bf16.bf16.f32 "
        "{%0,%1,%2,%3}, {%4,%5,%6,%7}, {%8,%9}, {%0,%1,%2,%3};"
        : "+f"(c[0]), "+f"(c[1]), "+f"(c[2]), "+f"(c[3])
        : "r"(a[0]), "r"(a[1]), "r"(a[2]), "r"(a[3]), "r"(b[0]), "r"(b[1]));
}

// split fp32 -> (hi, lo) bf16 pair packed as uint16
__device__ __forceinline__ void split_bf16(float x, uint16_t& hi, uint16_t& lo) {
    __nv_bfloat16 h = __float2bfloat16_rn(x);
    float hf = __bfloat162float(h);
    __nv_bfloat16 l = __float2bfloat16_rn(x - hf);
    hi = __bfloat16_as_ushort(h);
    lo = __bfloat16_as_ushort(l);
}

// ===========================================================================
// RoPE table init
// ===========================================================================
__global__ void rope_init(const int* __restrict__ tp) {
    int i = blockIdx.x * blockDim.x + threadIdx.x;  // 32*SEQL threads
    int p = i >> 11;
    int s = i & (SEQL - 1);
    float theta = 1.f / powf(10000.f, (2.f * p) * (1.f / 64.f));
    float ang = (float)tp[s] * theta;
    float sn, cs;
    sincosf(ang, &sn, &cs);
    g_rcos[i] = cs;
    g_rsin[i] = sn;
}

// ===========================================================================
// HMMA split-bf16 GEMM:  C[m,n] = sum_j A[m,j] * W[n,j]   (A @ W^T)
// 3 passes: hi*hi + hi*lo + lo*hi  (error ~2^-16, effectively fp32-class)
// CTA tile 128x128, BK=32, 8 warps (2x4), warp tile 64x32, double-buffered.
// mode 0: fused QKV (n0 in [0,3072), matrix = n0>>10), RoPE epi, [b,h,s,d]
// mode 3: plain row-major write to Dout
// ===========================================================================
#define BK 32
#define NCHUNK (D_MODEL / BK)       // 32
#define RSB 80                      // smem row stride bytes (16B-aligned, cf-free)
#define TILE_B (128 * RSB)          // 10240 per (matrix, hi/lo)
#define BUF_B (4 * TILE_B)          // A_hi A_lo W_hi W_lo
#define GEMM_SMEM (2 * BUF_B)       // 81920

__global__ __launch_bounds__(256, 1) void gemm_tc(
    const float* __restrict__ A,
    const float* __restrict__ W0, const float* __restrict__ W1,
    const float* __restrict__ W2,
    float* __restrict__ D0, float* __restrict__ D1, float* __restrict__ D2,
    float* __restrict__ Dout, int mode)
{
    extern __shared__ char smem[];
    uint32_t sb = smem_to_u32(smem);
    int tid = threadIdx.x;
    int wid = tid >> 5, lane = tid & 31;
    int m0 = blockIdx.y * 128;
    int n0 = blockIdx.x * 128;

    const float* W;
    int nw, mat = 0;
    if (mode == 3) { W = W0; nw = n0; }
    else {
        mat = n0 >> 10;
        nw = n0 & 1023;
        W = (mat == 0) ? W0 : (mat == 1) ? W1 : W2;
    }
    const float* Ap = A + (size_t)m0 * D_MODEL;
    const float* Wp = W + (size_t)nw * D_MODEL;

    // per-thread staging slots: kq fixed, rows r0 + 32*l
    int r0 = tid >> 3;
    int kq = tid & 7;

    float4 sa[4], sw[4];

    auto LDG = [&](int c) {
#pragma unroll
        for (int l = 0; l < 4; l++) {
            int r = r0 + 32 * l;
            sa[l] = *reinterpret_cast<const float4*>(
                Ap + (size_t)r * D_MODEL + c * BK + kq * 4);
            sw[l] = *reinterpret_cast<const float4*>(
                Wp + (size_t)r * D_MODEL + c * BK + kq * 4);
        }
    };

    auto STS = [&](int buf) {
        char* base = smem + buf * BUF_B;
#pragma unroll
        for (int l = 0; l < 4; l++) {
            int r = r0 + 32 * l;
            int off = r * RSB + kq * 8;
            uint16_t h0, h1, h2, h3, l0, l1, l2, l3;
            split_bf16(sa[l].x, h0, l0); split_bf16(sa[l].y, h1, l1);
            split_bf16(sa[l].z, h2, l2); split_bf16(sa[l].w, h3, l3);
            uint2 vh, vl;
            vh.x = (uint32_t)h0 | ((uint32_t)h1 << 16);
            vh.y = (uint32_t)h2 | ((uint32_t)h3 << 16);
            vl.x = (uint32_t)l0 | ((uint32_t)l1 << 16);
            vl.y = (uint32_t)l2 | ((uint32_t)l3 << 16);
            *reinterpret_cast<uint2*>(base + off) = vh;
            *reinterpret_cast<uint2*>(base + TILE_B + off) = vl;
            split_bf16(sw[l].x, h0, l0); split_bf16(sw[l].y, h1, l1);
            split_bf16(sw[l].z, h2, l2); split_bf16(sw[l].w, h3, l3);
            vh.x = (uint32_t)h0 | ((uint32_t)h1 << 16);
            vh.y = (uint32_t)h2 | ((uint32_t)h3 << 16);
            vl.x = (uint32_t)l0 | ((uint32_t)l1 << 16);
            vl.y = (uint32_t)l2 | ((uint32_t)l3 << 16);
            *reinterpret_cast<uint2*>(base + 2 * TILE_B + off) = vh;
            *reinterpret_cast<uint2*>(base + 3 * TILE_B + off) = vl;
        }
    };

    float acc[4][4][4];
#pragma unroll
    for (int i = 0; i < 4; i++)
#pragma unroll
        for (int j = 0; j < 4; j++)
#pragma unroll
            for (int k = 0; k < 4; k++) acc[i][j][k] = 0.f;

    int wm = (wid >> 2) * 64;
    int wn = (wid & 3) * 32;

    // ldmatrix per-lane address components
    int a_row = (lane & 7) + ((lane >> 3) & 1) * 8;   // 0..15
    int a_kof = (lane >> 4) * 16;                     // bytes
    int b_row = lane & 7;                             // lanes 0..15 matter
    int b_kof = ((lane >> 3) & 1) * 16;

    LDG(0); STS(0);
    __syncthreads();

    for (int c = 0; c < NCHUNK; c++) {
        if (c + 1 < NCHUNK) LDG(c + 1);

        uint32_t bufb = sb + (c & 1) * BUF_B;
#pragma unroll
        for (int kk = 0; kk < 2; kk++) {
            int kb = kk * 32;  // 16 bf16 = 32 bytes
            uint32_t ahi[4][4], alo[4][4];
#pragma unroll
            for (int mt = 0; mt < 4; mt++) {
                uint32_t ao = bufb + (wm + mt * 16 + a_row) * RSB + kb + a_kof;
                ldm_x4(ahi[mt], ao);
                ldm_x4(alo[mt], ao + TILE_B);
            }
            uint32_t bhi[4][2], blo[4][2];
#pragma unroll
            for (int nt = 0; nt < 4; nt++) {
                uint32_t bo = bufb + 2 * TILE_B +
                              (wn + nt * 8 + b_row) * RSB + kb + b_kof;
                ldm_x2(bhi[nt], bo);
                ldm_x2(blo[nt], bo + TILE_B);
            }
#pragma unroll
            for (int mt = 0; mt < 4; mt++)
#pragma unroll
                for (int nt = 0; nt < 4; nt++) {
                    mma_bf16(acc[mt][nt], ahi[mt], bhi[nt]);
                    mma_bf16(acc[mt][nt], ahi[mt], blo[nt]);
                    mma_bf16(acc[mt][nt], alo[mt], bhi[nt]);
                }
        }
        if (c + 1 < NCHUNK) STS((c + 1) & 1);
        __syncthreads();
    }

    // ---------------- epilogue ----------------
    int er = lane >> 2;            // 0..7
    int ec = (lane & 3) * 2;       // even col pair within 8

    if (mode == 3) {
#pragma unroll
        for (int mt = 0; mt < 4; mt++) {
            int m = m0 + wm + mt * 16 + er;
#pragma unroll
            for (int nt = 0; nt < 4; nt++) {
                int col = n0 + wn + nt * 8 + ec;
                float2 v0 = make_float2(acc[mt][nt][0], acc[mt][nt][1]);
                float2 v1 = make_float2(acc[mt][nt][2], acc[mt][nt][3]);
                *reinterpret_cast<float2*>(Dout + (size_t)m * D_MODEL + col) = v0;
                *reinterpret_cast<float2*>(Dout + (size_t)(m + 8) * D_MODEL + col) = v1;
            }
        }
        return;
    }

    float* Dst = (mat == 0) ? D0 : (mat == 1) ? D1 : D2;
#pragma unroll
    for (int mt = 0; mt < 4; mt++) {
        int m = m0 + wm + mt * 16 + er;
        int bi = m >> 11;
        int s0 = m & (SEQL - 1);
#pragma unroll
        for (int nt = 0; nt < 4; nt++) {
            int col = nw + wn + nt * 8 + ec;   // within this matrix
            int h = col >> 6, d = col & 63;
            int p = d >> 1;
#pragma unroll
            for (int rr = 0; rr < 2; rr++) {
                int s = s0 + rr * 8;
                float e0 = acc[mt][nt][rr * 2];
                float e1 = acc[mt][nt][rr * 2 + 1];
                float2 ov;
                if (mat != 2) {
                    float cs = g_rcos[p * SEQL + s];
                    float sn = g_rsin[p * SEQL + s];
                    ov.x = e0 * cs - e1 * sn;
                    ov.y = e0 * sn + e1 * cs;
                } else {
                    ov.x = e0; ov.y = e1;
                }
                size_t o = (((size_t)(bi * NH + h)) * SEQL + s) * HD + d;
                *reinterpret_cast<float2*>(Dst + o) = ov;
            }
        }
    }
}

// ---------------------------------------------------------------------------
// Flash attention (fp32, online softmax) — unchanged from passing R1 kernel
// except expf -> __expf.
// ---------------------------------------------------------------------------
#define ATTN_SMEM (4 * 64 * 65 * (int)sizeof(float))

__global__ __launch_bounds__(256) void attn_kernel()
{
    extern __shared__ float sm[];
    float* Qs = sm;
    float* Ks = sm + 64 * 65;
    float* Vs = sm + 2 * 64 * 65;
    float* Ps = sm + 3 * 64 * 65;

    int bh = blockIdx.y;
    int qt = gridDim.x - 1 - blockIdx.x;
    int tid = threadIdx.x;
    int tx = tid & 15, ty = tid >> 4;

    const float* qp = g_q + (size_t)bh * SEQL * HD + (size_t)qt * 64 * HD;
    const float* kp = g_k + (size_t)bh * SEQL * HD;
    const float* vp = g_v + (size_t)bh * SEQL * HD;

#pragma unroll
    for (int l = 0; l < 4; l++) {
        int idx4 = tid + l * 256;
        int r = idx4 >> 4;
        int dc = (idx4 & 15) << 2;
        float4 qv = *reinterpret_cast<const float4*>(qp + r * HD + dc);
        Qs[r * 65 + dc + 0] = qv.x; Qs[r * 65 + dc + 1] = qv.y;
        Qs[r * 65 + dc + 2] = qv.z; Qs[r * 65 + dc + 3] = qv.w;
    }

    float o[4][4];
    float mr[4], lr[4];
#pragma unroll
    for (int i = 0; i < 4; i++) {
        mr[i] = -1e30f; lr[i] = 0.f;
#pragma unroll
        for (int j = 0; j < 4; j++) o[i][j] = 0.f;
    }

    for (int t = 0; t <= qt; t++) {
        __syncthreads();
        const float* kt = kp + (size_t)t * 64 * HD;
        const float* vt = vp + (size_t)t * 64 * HD;
#pragma unroll
        for (int l = 0; l < 4; l++) {
            int idx4 = tid + l * 256;
            int r = idx4 >> 4;
            int dc = (idx4 & 15) << 2;
            float4 kv = *reinterpret_cast<const float4*>(kt + r * HD + dc);
            Ks[r * 65 + dc + 0] = kv.x; Ks[r * 65 + dc + 1] = kv.y;
            Ks[r * 65 + dc + 2] = kv.z; Ks[r * 65 + dc + 3] = kv.w;
            float4 vv = *reinterpret_cast<const float4*>(vt + r * HD + dc);
            Vs[r * 65 + dc + 0] = vv.x; Vs[r * 65 + dc + 1] = vv.y;
            Vs[r * 65 + dc + 2] = vv.z; Vs[r * 65 + dc + 3] = vv.w;
        }
        __syncthreads();

        float sc[4][4];
#pragma unroll
        for (int i = 0; i < 4; i++)
#pragma unroll
            for (int j = 0; j < 4; j++) sc[i][j] = 0.f;

#pragma unroll 8
        for (int d = 0; d < HD; d++) {
            float qa[4], kb[4];
#pragma unroll
            for (int i = 0; i < 4; i++) qa[i] = Qs[(ty * 4 + i) * 65 + d];
#pragma unroll
            for (int j = 0; j < 4; j++) kb[j] = Ks[(tx * 4 + j) * 65 + d];
#pragma unroll
            for (int i = 0; i < 4; i++)
#pragma unroll
                for (int j = 0; j < 4; j++)
                    sc[i][j] = fmaf(qa[i], kb[j], sc[i][j]);
        }

        bool diag = (t == qt);
#pragma unroll
        for (int i = 0; i < 4; i++) {
            int r = ty * 4 + i;
#pragma unroll
            for (int j = 0; j < 4; j++) {
                int c = tx * 4 + j;
                sc[i][j] = (diag && c > r) ? -1e30f : sc[i][j] * 0.125f;
            }
        }

#pragma unroll
        for (int i = 0; i < 4; i++) {
            float tm = fmaxf(fmaxf(sc[i][0], sc[i][1]),
                             fmaxf(sc[i][2], sc[i][3]));
#pragma unroll
            for (int off = 8; off > 0; off >>= 1)
                tm = fmaxf(tm, __shfl_xor_sync(0xffffffffu, tm, off));
            float mn = fmaxf(mr[i], tm);
            float corr = __expf(mr[i] - mn);
            mr[i] = mn;
            float rs = 0.f;
#pragma unroll
            for (int j = 0; j < 4; j++) {
                sc[i][j] = __expf(sc[i][j] - mn);
                rs += sc[i][j];
            }
#pragma unroll
            for (int off = 8; off > 0; off >>= 1)
                rs += __shfl_xor_sync(0xffffffffu, rs, off);
            lr[i] = lr[i] * corr + rs;
#pragma unroll
            for (int j = 0; j < 4; j++) {
                o[i][j] *= corr;
                Ps[(ty * 4 + i) * 65 + tx * 4 + j] = sc[i][j];
            }
        }
        __syncthreads();

#pragma unroll 8
        for (int c = 0; c < 64; c++) {
            float pa[4], vb[4];
#pragma unroll
            for (int i = 0; i < 4; i++) pa[i] = Ps[(ty * 4 + i) * 65 + c];
#pragma unroll
            for (int j = 0; j < 4; j++) vb[j] = Vs[c * 65 + tx * 4 + j];
#pragma unroll
            for (int i = 0; i < 4; i++)
#pragma unroll
                for (int j = 0; j < 4; j++)
                    o[i][j] = fmaf(pa[i], vb[j], o[i][j]);
        }
    }

    int b = bh >> 4, h = bh & 15;
#pragma unroll
    for (int i = 0; i < 4; i++) {
        float inv = 1.f / lr[i];
        int s = qt * 64 + ty * 4 + i;
        size_t base = ((size_t)b * SEQL + s) * D_MODEL + h * HD + tx * 4;
#pragma unroll
        for (int j = 0; j < 4; j++) g_attn[base + j] = o[i][j] * inv;
    }
}

// ---------------------------------------------------------------------------
extern "C" void kernel_launch(void* const* d_in, const int* in_sizes, int n_in,
                              void* d_out, int out_size)
{
    const float* x  = (const float*)d_in[0];
    const int*   tp = (const int*)d_in[1];
    const float* wq = (const float*)d_in[2];
    const float* wk = (const float*)d_in[3];
    const float* wv = (const float*)d_in[4];
    const float* wo = (const float*)d_in[5];
    float* out = (float*)d_out;

    float *qg, *kg, *vg, *ag;
    cudaGetSymbolAddress((void**)&qg, g_q);
    cudaGetSymbolAddress((void**)&kg, g_k);
    cudaGetSymbolAddress((void**)&vg, g_v);
    cudaGetSymbolAddress((void**)&ag, g_attn);

    cudaFuncSetAttribute(gemm_tc,
                         cudaFuncAttributeMaxDynamicSharedMemorySize,
                         GEMM_SMEM);
    cudaFuncSetAttribute(attn_kernel,
                         cudaFuncAttributeMaxDynamicSharedMemorySize,
                         ATTN_SMEM);

    // RoPE cos/sin table
    rope_init<<<(32 * SEQL) / 256, 256>>>(tp);

    // fused QKV projection (N = 3072 stacked) + RoPE epilogue
    dim3 gqkv(3 * D_MODEL / 128, MTOT / 128);
    gemm_tc<<<gqkv, 256, GEMM_SMEM>>>(x, wq, wk, wv, qg, kg, vg, nullptr, 0);

    // causal flash attention
    dim3 gattn(SEQL / 64, BATCH * NH);
    attn_kernel<<<gattn, 256, ATTN_SMEM>>>();

    // output projection
    dim3 gproj(D_MODEL / 128, MTOT / 128);
    gemm_tc<<<gproj, 256, GEMM_SMEM>>>(ag, wo, nullptr, nullptr,
                                       nullptr, nullptr, nullptr, out, 3);
}

// round 4
// speedup vs baseline: 2.4980x; 1.6809x over previous
#include <cuda_runtime.h>
#include <cuda_bf16.h>
#include <math.h>
#include <cstdint>

#define D_MODEL 1024
#define NH 16
#define HD 64
#define SEQL 2048
#define BATCH 4
#define MTOT (BATCH * SEQL)

// Scratch (static device globals — allocation-free per harness rules)
__device__ float g_q[(size_t)BATCH * NH * SEQL * HD];
__device__ float g_k[(size_t)BATCH * NH * SEQL * HD];
__device__ float g_v[(size_t)BATCH * NH * SEQL * HD];
__device__ float g_attn[(size_t)MTOT * D_MODEL];
__device__ float g_rcos[32 * SEQL];   // [p][s]
__device__ float g_rsin[32 * SEQL];

// ===========================================================================
// helpers
// ===========================================================================
__device__ __forceinline__ uint32_t smem_to_u32(const void* p) {
    uint32_t a;
    asm("{ .reg .u64 t; cvta.to.shared.u64 t, %1; cvt.u32.u64 %0, t; }"
        : "=r"(a) : "l"(p));
    return a;
}

__device__ __forceinline__ void ldm_x4(uint32_t* r, uint32_t addr) {
    asm volatile("ldmatrix.sync.aligned.m8n8.x4.shared.b16 {%0,%1,%2,%3}, [%4];"
                 : "=r"(r[0]), "=r"(r[1]), "=r"(r[2]), "=r"(r[3]) : "r"(addr));
}
__device__ __forceinline__ void ldm_x4_t(uint32_t* r, uint32_t addr) {
    asm volatile("ldmatrix.sync.aligned.m8n8.x4.trans.shared.b16 {%0,%1,%2,%3}, [%4];"
                 : "=r"(r[0]), "=r"(r[1]), "=r"(r[2]), "=r"(r[3]) : "r"(addr));
}
__device__ __forceinline__ void ldm_x2(uint32_t* r, uint32_t addr) {
    asm volatile("ldmatrix.sync.aligned.m8n8.x2.shared.b16 {%0,%1}, [%2];"
                 : "=r"(r[0]), "=r"(r[1]) : "r"(addr));
}

__device__ __forceinline__ void mma_bf16(float* c, const uint32_t* a,
                                         const uint32_t* b) {
    asm volatile(
        "mma.sync.aligned.m16n8k16.row.col.f32.bf16.bf16.f32 "
        "{%0,%1,%2,%3}, {%4,%5,%6,%7}, {%8,%9}, {%0,%1,%2,%3};"
        : "+f"(c[0]), "+f"(c[1]), "+f"(c[2]), "+f"(c[3])
        : "r"(a[0]), "r"(a[1]), "r"(a[2]), "r"(a[3]), "r"(b[0]), "r"(b[1]));
}

__device__ __forceinline__ float ex2f(float x) {
    float y;
    asm("ex2.approx.f32 %0, %1;" : "=f"(y) : "f"(x));
    return y;
}

// split fp32 -> (hi, lo) bf16 pair
__device__ __forceinline__ void split_bf16(float x, uint16_t& hi, uint16_t& lo) {
    __nv_bfloat16 h = __float2bfloat16_rn(x);
    float hf = __bfloat162float(h);
    __nv_bfloat16 l = __float2bfloat16_rn(x - hf);
    hi = __bfloat16_as_ushort(h);
    lo = __bfloat16_as_ushort(l);
}

__device__ __forceinline__ void split4(const float4& v, uint2& vh, uint2& vl) {
    uint16_t h0, h1, h2, h3, l0, l1, l2, l3;
    split_bf16(v.x, h0, l0); split_bf16(v.y, h1, l1);
    split_bf16(v.z, h2, l2); split_bf16(v.w, h3, l3);
    vh.x = (uint32_t)h0 | ((uint32_t)h1 << 16);
    vh.y = (uint32_t)h2 | ((uint32_t)h3 << 16);
    vl.x = (uint32_t)l0 | ((uint32_t)l1 << 16);
    vl.y = (uint32_t)l2 | ((uint32_t)l3 << 16);
}

__device__ __forceinline__ void pack2_hl(float x, float y,
                                         uint32_t& h, uint32_t& l) {
    uint16_t hx, lx, hy, ly;
    split_bf16(x, hx, lx);
    split_bf16(y, hy, ly);
    h = (uint32_t)hx | ((uint32_t)hy << 16);
    l = (uint32_t)lx | ((uint32_t)ly << 16);
}

// ===========================================================================
// RoPE table init
// ===========================================================================
__global__ void rope_init(const int* __restrict__ tp) {
    int i = blockIdx.x * blockDim.x + threadIdx.x;
    int p = i >> 11;
    int s = i & (SEQL - 1);
    float theta = 1.f / powf(10000.f, (2.f * p) * (1.f / 64.f));
    float ang = (float)tp[s] * theta;
    float sn, cs;
    sincosf(ang, &sn, &cs);
    g_rcos[i] = cs;
    g_rsin[i] = sn;
}

// ===========================================================================
// HMMA split-bf16 GEMM (unchanged from R3 passing version)
// ===========================================================================
#define BK 32
#define NCHUNK (D_MODEL / BK)
#define RSB 80
#define TILE_B (128 * RSB)
#define BUF_B (4 * TILE_B)
#define GEMM_SMEM (2 * BUF_B)

__global__ __launch_bounds__(256, 1) void gemm_tc(
    const float* __restrict__ A,
    const float* __restrict__ W0, const float* __restrict__ W1,
    const float* __restrict__ W2,
    float* __restrict__ D0, float* __restrict__ D1, float* __restrict__ D2,
    float* __restrict__ Dout, int mode)
{
    extern __shared__ char smem[];
    uint32_t sb = smem_to_u32(smem);
    int tid = threadIdx.x;
    int wid = tid >> 5, lane = tid & 31;
    int m0 = blockIdx.y * 128;
    int n0 = blockIdx.x * 128;

    const float* W;
    int nw, mat = 0;
    if (mode == 3) { W = W0; nw = n0; }
    else {
        mat = n0 >> 10;
        nw = n0 & 1023;
        W = (mat == 0) ? W0 : (mat == 1) ? W1 : W2;
    }
    const float* Ap = A + (size_t)m0 * D_MODEL;
    const float* Wp = W + (size_t)nw * D_MODEL;

    int r0 = tid >> 3;
    int kq = tid & 7;

    float4 sa[4], sw[4];

    auto LDG = [&](int c) {
#pragma unroll
        for (int l = 0; l < 4; l++) {
            int r = r0 + 32 * l;
            sa[l] = *reinterpret_cast<const float4*>(
                Ap + (size_t)r * D_MODEL + c * BK + kq * 4);
            sw[l] = *reinterpret_cast<const float4*>(
                Wp + (size_t)r * D_MODEL + c * BK + kq * 4);
        }
    };

    auto STS = [&](int buf) {
        char* base = smem + buf * BUF_B;
#pragma unroll
        for (int l = 0; l < 4; l++) {
            int r = r0 + 32 * l;
            int off = r * RSB + kq * 8;
            uint2 vh, vl;
            split4(sa[l], vh, vl);
            *reinterpret_cast<uint2*>(base + off) = vh;
            *reinterpret_cast<uint2*>(base + TILE_B + off) = vl;
            split4(sw[l], vh, vl);
            *reinterpret_cast<uint2*>(base + 2 * TILE_B + off) = vh;
            *reinterpret_cast<uint2*>(base + 3 * TILE_B + off) = vl;
        }
    };

    float acc[4][4][4];
#pragma unroll
    for (int i = 0; i < 4; i++)
#pragma unroll
        for (int j = 0; j < 4; j++)
#pragma unroll
            for (int k = 0; k < 4; k++) acc[i][j][k] = 0.f;

    int wm = (wid >> 2) * 64;
    int wn = (wid & 3) * 32;

    int a_row = (lane & 7) + ((lane >> 3) & 1) * 8;
    int a_kof = (lane >> 4) * 16;
    int b_row = lane & 7;
    int b_kof = ((lane >> 3) & 1) * 16;

    LDG(0); STS(0);
    __syncthreads();

    for (int c = 0; c < NCHUNK; c++) {
        if (c + 1 < NCHUNK) LDG(c + 1);

        uint32_t bufb = sb + (c & 1) * BUF_B;
#pragma unroll
        for (int kk = 0; kk < 2; kk++) {
            int kb = kk * 32;
            uint32_t ahi[4][4], alo[4][4];
#pragma unroll
            for (int mt = 0; mt < 4; mt++) {
                uint32_t ao = bufb + (wm + mt * 16 + a_row) * RSB + kb + a_kof;
                ldm_x4(ahi[mt], ao);
                ldm_x4(alo[mt], ao + TILE_B);
            }
            uint32_t bhi[4][2], blo[4][2];
#pragma unroll
            for (int nt = 0; nt < 4; nt++) {
                uint32_t bo = bufb + 2 * TILE_B +
                              (wn + nt * 8 + b_row) * RSB + kb + b_kof;
                ldm_x2(bhi[nt], bo);
                ldm_x2(blo[nt], bo + TILE_B);
            }
#pragma unroll
            for (int mt = 0; mt < 4; mt++)
#pragma unroll
                for (int nt = 0; nt < 4; nt++) {
                    mma_bf16(acc[mt][nt], ahi[mt], bhi[nt]);
                    mma_bf16(acc[mt][nt], ahi[mt], blo[nt]);
                    mma_bf16(acc[mt][nt], alo[mt], bhi[nt]);
                }
        }
        if (c + 1 < NCHUNK) STS((c + 1) & 1);
        __syncthreads();
    }

    int er = lane >> 2;
    int ec = (lane & 3) * 2;

    if (mode == 3) {
#pragma unroll
        for (int mt = 0; mt < 4; mt++) {
            int m = m0 + wm + mt * 16 + er;
#pragma unroll
            for (int nt = 0; nt < 4; nt++) {
                int col = n0 + wn + nt * 8 + ec;
                float2 v0 = make_float2(acc[mt][nt][0], acc[mt][nt][1]);
                float2 v1 = make_float2(acc[mt][nt][2], acc[mt][nt][3]);
                *reinterpret_cast<float2*>(Dout + (size_t)m * D_MODEL + col) = v0;
                *reinterpret_cast<float2*>(Dout + (size_t)(m + 8) * D_MODEL + col) = v1;
            }
        }
        return;
    }

    float* Dst = (mat == 0) ? D0 : (mat == 1) ? D1 : D2;
#pragma unroll
    for (int mt = 0; mt < 4; mt++) {
        int m = m0 + wm + mt * 16 + er;
        int bi = m >> 11;
        int s0 = m & (SEQL - 1);
#pragma unroll
        for (int nt = 0; nt < 4; nt++) {
            int col = nw + wn + nt * 8 + ec;
            int h = col >> 6, d = col & 63;
            int p = d >> 1;
#pragma unroll
            for (int rr = 0; rr < 2; rr++) {
                int s = s0 + rr * 8;
                float e0 = acc[mt][nt][rr * 2];
                float e1 = acc[mt][nt][rr * 2 + 1];
                float2 ov;
                if (mat != 2) {
                    float cs = g_rcos[p * SEQL + s];
                    float sn = g_rsin[p * SEQL + s];
                    ov.x = e0 * cs - e1 * sn;
                    ov.y = e0 * sn + e1 * cs;
                } else {
                    ov.x = e0; ov.y = e1;
                }
                size_t o = (((size_t)(bi * NH + h)) * SEQL + s) * HD + d;
                *reinterpret_cast<float2*>(Dst + o) = ov;
            }
        }
    }
}

// ===========================================================================
// HMMA flash attention, split-bf16 (3-pass QK^T and PV), online softmax.
// CTA: 128 q-rows, 8 warps (16 rows each). K/V tiles: 64 keys.
// Smem rows stride 144 B (9*16 -> conflict-free ldmatrix).
// ===========================================================================
#define ARS 144
#define QHI_OFF 0
#define QLO_OFF (128 * ARS)
#define KHI_OFF (2 * 128 * ARS)
#define KLO_OFF (KHI_OFF + 64 * ARS)
#define VHI_OFF (KLO_OFF + 64 * ARS)
#define VLO_OFF (VHI_OFF + 64 * ARS)
#define ATTN_SMEM (VLO_OFF + 64 * ARS)   // 73728

#define SC2 0.180336880f   /* (1/8) * log2(e) */

__global__ __launch_bounds__(256, 2) void attn_tc()
{
    extern __shared__ char sm[];
    uint32_t sb = smem_to_u32(sm);
    int tid = threadIdx.x;
    int lane = tid & 31, w = tid >> 5;
    int bh = blockIdx.y;
    int qti = gridDim.x - 1 - blockIdx.x;   // long tiles first
    int qm0 = qti * 128;

    const float* qp = g_q + (size_t)bh * SEQL * HD + (size_t)qm0 * HD;
    const float* kp = g_k + (size_t)bh * SEQL * HD;
    const float* vp = g_v + (size_t)bh * SEQL * HD;

    // ---- load Q tile (fp32 -> bf16 hi/lo in smem) ----
#pragma unroll
    for (int l = 0; l < 8; l++) {
        int idx = tid + l * 256;      // 0..2047
        int row = idx >> 4;
        int dc = idx & 15;
        float4 v = *reinterpret_cast<const float4*>(qp + row * HD + dc * 4);
        uint2 vh, vl;
        split4(v, vh, vl);
        *reinterpret_cast<uint2*>(sm + QHI_OFF + row * ARS + dc * 8) = vh;
        *reinterpret_cast<uint2*>(sm + QLO_OFF + row * ARS + dc * 8) = vl;
    }

    float o[8][4];
#pragma unroll
    for (int i = 0; i < 8; i++)
#pragma unroll
        for (int j = 0; j < 4; j++) o[i][j] = 0.f;
    float m0 = -1e30f, m1 = -1e30f, l0 = 0.f, l1 = 0.f;

    int er = lane >> 2;
    int ec2 = (lane & 3) * 2;
    int row_g0 = qm0 + w * 16 + er;   // global q row (c0/c1)
    int row_g1 = row_g0 + 8;          // (c2/c3)

    // ldmatrix lane addressing
    uint32_t a_addr = sb + QHI_OFF +
                      (w * 16 + (lane & 15)) * ARS + (lane >> 4) * 16;
    // K b-frag x4 (2 n-groups x k16): rows = ((lane>>4)&1)*8 + (lane&7),
    // kof = ((lane>>3)&1)*16
    uint32_t kb_row = ((lane >> 4) & 1) * 8 + (lane & 7);
    uint32_t kb_kof = ((lane >> 3) & 1) * 16;
    // V x4 trans (1 kchunk x 2 n-groups): key = (lane&7)+((lane>>3)&1)*8,
    // dim byte off = ((lane>>4)&1)*16
    uint32_t v_key = (lane & 7) + ((lane >> 3) & 1) * 8;
    uint32_t v_dof = ((lane >> 4) & 1) * 16;

    int nkt = 2 * qti + 2;
    for (int kt = 0; kt < nkt; kt++) {
        __syncthreads();
        // ---- load K/V tile kt ----
        {
            const float* ktp = kp + (size_t)kt * 64 * HD;
            const float* vtp = vp + (size_t)kt * 64 * HD;
#pragma unroll
            for (int l = 0; l < 4; l++) {
                int idx = tid + l * 256;   // 0..1023
                int row = idx >> 4;
                int dc = idx & 15;
                float4 kv = *reinterpret_cast<const float4*>(ktp + row * HD + dc * 4);
                uint2 vh, vl;
                split4(kv, vh, vl);
                *reinterpret_cast<uint2*>(sm + KHI_OFF + row * ARS + dc * 8) = vh;
                *reinterpret_cast<uint2*>(sm + KLO_OFF + row * ARS + dc * 8) = vl;
                float4 vv = *reinterpret_cast<const float4*>(vtp + row * HD + dc * 4);
                split4(vv, vh, vl);
                *reinterpret_cast<uint2*>(sm + VHI_OFF + row * ARS + dc * 8) = vh;
                *reinterpret_cast<uint2*>(sm + VLO_OFF + row * ARS + dc * 8) = vl;
            }
        }
        __syncthreads();

        // ---- S = Q K^T (16 x 64 per warp), 3-pass split-bf16 ----
        float sc[8][4];
#pragma unroll
        for (int i = 0; i < 8; i++)
#pragma unroll
            for (int j = 0; j < 4; j++) sc[i][j] = 0.f;

#pragma unroll
        for (int kk = 0; kk < 4; kk++) {
            uint32_t qh[4], ql[4];
            ldm_x4(qh, a_addr + kk * 32);
            ldm_x4(ql, a_addr + kk * 32 + (QLO_OFF - QHI_OFF));
#pragma unroll
            for (int ntp = 0; ntp < 4; ntp++) {
                uint32_t bh4[4], bl4[4];
                uint32_t ka = sb + KHI_OFF +
                              (ntp * 16 + kb_row) * ARS + kk * 32 + kb_kof;
                ldm_x4(bh4, ka);
                ldm_x4(bl4, ka + (KLO_OFF - KHI_OFF));
                mma_bf16(sc[2 * ntp],     qh, bh4);
                mma_bf16(sc[2 * ntp],     qh, bl4);
                mma_bf16(sc[2 * ntp],     ql, bh4);
                mma_bf16(sc[2 * ntp + 1], qh, bh4 + 2);
                mma_bf16(sc[2 * ntp + 1], qh, bl4 + 2);
                mma_bf16(sc[2 * ntp + 1], ql, bh4 + 2);
            }
        }

        // ---- scale + causal mask (log2 domain) ----
        bool diag = (kt >= 2 * qti);
#pragma unroll
        for (int nt = 0; nt < 8; nt++) {
            int c0 = kt * 64 + nt * 8 + ec2;
            if (diag) {
                sc[nt][0] = (c0     > row_g0) ? -1e30f : sc[nt][0] * SC2;
                sc[nt][1] = (c0 + 1 > row_g0) ? -1e30f : sc[nt][1] * SC2;
                sc[nt][2] = (c0     > row_g1) ? -1e30f : sc[nt][2] * SC2;
                sc[nt][3] = (c0 + 1 > row_g1) ? -1e30f : sc[nt][3] * SC2;
            } else {
                sc[nt][0] *= SC2; sc[nt][1] *= SC2;
                sc[nt][2] *= SC2; sc[nt][3] *= SC2;
            }
        }

        // ---- online softmax (rows er / er+8; quad = lanes sharing row) ----
        float tm0 = -1e30f, tm1 = -1e30f;
#pragma unroll
        for (int nt = 0; nt < 8; nt++) {
            tm0 = fmaxf(tm0, fmaxf(sc[nt][0], sc[nt][1]));
            tm1 = fmaxf(tm1, fmaxf(sc[nt][2], sc[nt][3]));
        }
        tm0 = fmaxf(tm0, __shfl_xor_sync(0xffffffffu, tm0, 1));
        tm0 = fmaxf(tm0, __shfl_xor_sync(0xffffffffu, tm0, 2));
        tm1 = fmaxf(tm1, __shfl_xor_sync(0xffffffffu, tm1, 1));
        tm1 = fmaxf(tm1, __shfl_xor_sync(0xffffffffu, tm1, 2));
        float mn0 = fmaxf(m0, tm0), mn1 = fmaxf(m1, tm1);
        float cf0 = ex2f(m0 - mn0), cf1 = ex2f(m1 - mn1);
        m0 = mn0; m1 = mn1;

        float rs0 = 0.f, rs1 = 0.f;
#pragma unroll
        for (int nt = 0; nt < 8; nt++) {
            float p0 = ex2f(sc[nt][0] - mn0);
            float p1 = ex2f(sc[nt][1] - mn0);
            float p2 = ex2f(sc[nt][2] - mn1);
            float p3 = ex2f(sc[nt][3] - mn1);
            sc[nt][0] = p0; sc[nt][1] = p1; sc[nt][2] = p2; sc[nt][3] = p3;
            rs0 += p0 + p1;
            rs1 += p2 + p3;
        }
        rs0 += __shfl_xor_sync(0xffffffffu, rs0, 1);
        rs0 += __shfl_xor_sync(0xffffffffu, rs0, 2);
        rs1 += __shfl_xor_sync(0xffffffffu, rs1, 1);
        rs1 += __shfl_xor_sync(0xffffffffu, rs1, 2);
        l0 = l0 * cf0 + rs0;
        l1 = l1 * cf1 + rs1;
#pragma unroll
        for (int ng = 0; ng < 8; ng++) {
            o[ng][0] *= cf0; o[ng][1] *= cf0;
            o[ng][2] *= cf1; o[ng][3] *= cf1;
        }

        // ---- O += P V  (3-pass split-bf16, P repacked in-register) ----
#pragma unroll
        for (int kk = 0; kk < 4; kk++) {
            uint32_t ph[4], pl[4];
            pack2_hl(sc[2 * kk][0],     sc[2 * kk][1],     ph[0], pl[0]);
            pack2_hl(sc[2 * kk][2],     sc[2 * kk][3],     ph[1], pl[1]);
            pack2_hl(sc[2 * kk + 1][0], sc[2 * kk + 1][1], ph[2], pl[2]);
            pack2_hl(sc[2 * kk + 1][2], sc[2 * kk + 1][3], ph[3], pl[3]);
#pragma unroll
            for (int ngp = 0; ngp < 4; ngp++) {
                uint32_t vh4[4], vl4[4];
                uint32_t va = sb + VHI_OFF +
                              (kk * 16 + v_key) * ARS + ngp * 32 + v_dof;
                ldm_x4_t(vh4, va);
                ldm_x4_t(vl4, va + (VLO_OFF - VHI_OFF));
                mma_bf16(o[2 * ngp],     ph, vh4);
                mma_bf16(o[2 * ngp],     ph, vl4);
                mma_bf16(o[2 * ngp],     pl, vh4);
                mma_bf16(o[2 * ngp + 1], ph, vh4 + 2);
                mma_bf16(o[2 * ngp + 1], ph, vl4 + 2);
                mma_bf16(o[2 * ngp + 1], pl, vh4 + 2);
            }
        }
    }

    // ---- write O/l to g_attn [b, s, h*64+d] ----
    int bi = bh >> 4, h = bh & 15;
    float inv0 = 1.f / l0, inv1 = 1.f / l1;
    int s0 = qm0 + w * 16 + er;
#pragma unroll
    for (int ng = 0; ng < 8; ng++) {
        int d = h * 64 + ng * 8 + ec2;
        float2 v0 = make_float2(o[ng][0] * inv0, o[ng][1] * inv0);
        float2 v1 = make_float2(o[ng][2] * inv1, o[ng][3] * inv1);
        *reinterpret_cast<float2*>(
            g_attn + ((size_t)bi * SEQL + s0) * D_MODEL + d) = v0;
        *reinterpret_cast<float2*>(
            g_attn + ((size_t)bi * SEQL + s0 + 8) * D_MODEL + d) = v1;
    }
}

// ---------------------------------------------------------------------------
extern "C" void kernel_launch(void* const* d_in, const int* in_sizes, int n_in,
                              void* d_out, int out_size)
{
    const float* x  = (const float*)d_in[0];
    const int*   tp = (const int*)d_in[1];
    const float* wq = (const float*)d_in[2];
    const float* wk = (const float*)d_in[3];
    const float* wv = (const float*)d_in[4];
    const float* wo = (const float*)d_in[5];
    float* out = (float*)d_out;

    float *qg, *kg, *vg, *ag;
    cudaGetSymbolAddress((void**)&qg, g_q);
    cudaGetSymbolAddress((void**)&kg, g_k);
    cudaGetSymbolAddress((void**)&vg, g_v);
    cudaGetSymbolAddress((void**)&ag, g_attn);

    cudaFuncSetAttribute(gemm_tc,
                         cudaFuncAttributeMaxDynamicSharedMemorySize,
                         GEMM_SMEM);
    cudaFuncSetAttribute(attn_tc,
                         cudaFuncAttributeMaxDynamicSharedMemorySize,
                         ATTN_SMEM);

    // RoPE cos/sin table
    rope_init<<<(32 * SEQL) / 256, 256>>>(tp);

    // fused QKV projection (N = 3072 stacked) + RoPE epilogue
    dim3 gqkv(3 * D_MODEL / 128, MTOT / 128);
    gemm_tc<<<gqkv, 256, GEMM_SMEM>>>(x, wq, wk, wv, qg, kg, vg, nullptr, 0);

    // causal flash attention (HMMA)
    dim3 gattn(SEQL / 128, BATCH * NH);
    attn_tc<<<gattn, 256, ATTN_SMEM>>>();

    // output projection
    dim3 gproj(D_MODEL / 128, MTOT / 128);
    gemm_tc<<<gproj, 256, GEMM_SMEM>>>(ag, wo, nullptr, nullptr,
                                       nullptr, nullptr, nullptr, out, 3);
}

// round 5
// speedup vs baseline: 2.6602x; 1.0649x over previous
#include <cuda_runtime.h>
#include <cuda_bf16.h>
#include <math.h>
#include <cstdint>

#define D_MODEL 1024
#define NH 16
#define HD 64
#define SEQL 2048
#define BATCH 4
#define MTOT (BATCH * SEQL)

// Scratch (static device globals — allocation-free per harness rules)
// Q/K/V stored pre-split as bf16 hi/lo, layout [bh][s][64]
#define QKV_ELEMS ((size_t)BATCH * NH * SEQL * HD)
__device__ __nv_bfloat16 g_qh[QKV_ELEMS], g_ql[QKV_ELEMS];
__device__ __nv_bfloat16 g_kh[QKV_ELEMS], g_kl[QKV_ELEMS];
__device__ __nv_bfloat16 g_vh[QKV_ELEMS], g_vl[QKV_ELEMS];
__device__ float g_attn[(size_t)MTOT * D_MODEL];
__device__ float g_rcos[32 * SEQL];   // [p][s]
__device__ float g_rsin[32 * SEQL];

// ===========================================================================
// helpers
// ===========================================================================
__device__ __forceinline__ uint32_t smem_to_u32(const void* p) {
    uint32_t a;
    asm("{ .reg .u64 t; cvta.to.shared.u64 t, %1; cvt.u32.u64 %0, t; }"
        : "=r"(a) : "l"(p));
    return a;
}

__device__ __forceinline__ void ldm_x4(uint32_t* r, uint32_t addr) {
    asm volatile("ldmatrix.sync.aligned.m8n8.x4.shared.b16 {%0,%1,%2,%3}, [%4];"
                 : "=r"(r[0]), "=r"(r[1]), "=r"(r[2]), "=r"(r[3]) : "r"(addr));
}
__device__ __forceinline__ void ldm_x4_t(uint32_t* r, uint32_t addr) {
    asm volatile("ldmatrix.sync.aligned.m8n8.x4.trans.shared.b16 {%0,%1,%2,%3}, [%4];"
                 : "=r"(r[0]), "=r"(r[1]), "=r"(r[2]), "=r"(r[3]) : "r"(addr));
}
__device__ __forceinline__ void ldm_x2(uint32_t* r, uint32_t addr) {
    asm volatile("ldmatrix.sync.aligned.m8n8.x2.shared.b16 {%0,%1}, [%2];"
                 : "=r"(r[0]), "=r"(r[1]) : "r"(addr));
}

__device__ __forceinline__ void mma_bf16(float* c, const uint32_t* a,
                                         const uint32_t* b) {
    asm volatile(
        "mma.sync.aligned.m16n8k16.row.col.f32.bf16.bf16.f32 "
        "{%0,%1,%2,%3}, {%4,%5,%6,%7}, {%8,%9}, {%0,%1,%2,%3};"
        : "+f"(c[0]), "+f"(c[1]), "+f"(c[2]), "+f"(c[3])
        : "r"(a[0]), "r"(a[1]), "r"(a[2]), "r"(a[3]), "r"(b[0]), "r"(b[1]));
}

__device__ __forceinline__ float ex2f(float x) {
    float y;
    asm("ex2.approx.f32 %0, %1;" : "=f"(y) : "f"(x));
    return y;
}

#define CP_ASYNC16(dst, src) \
    asm volatile("cp.async.cg.shared.global [%0], [%1], 16;" \
                 :: "r"(dst), "l"(src) : "memory")
#define CP_COMMIT() asm volatile("cp.async.commit_group;" ::: "memory")
#define CP_WAIT(n)  asm volatile("cp.async.wait_group %0;" :: "n"(n) : "memory")

// split fp32 -> (hi, lo) bf16 pair
__device__ __forceinline__ void split_bf16(float x, uint16_t& hi, uint16_t& lo) {
    __nv_bfloat16 h = __float2bfloat16_rn(x);
    float hf = __bfloat162float(h);
    __nv_bfloat16 l = __float2bfloat16_rn(x - hf);
    hi = __bfloat16_as_ushort(h);
    lo = __bfloat16_as_ushort(l);
}

__device__ __forceinline__ void split4(const float4& v, uint2& vh, uint2& vl) {
    uint16_t h0, h1, h2, h3, l0, l1, l2, l3;
    split_bf16(v.x, h0, l0); split_bf16(v.y, h1, l1);
    split_bf16(v.z, h2, l2); split_bf16(v.w, h3, l3);
    vh.x = (uint32_t)h0 | ((uint32_t)h1 << 16);
    vh.y = (uint32_t)h2 | ((uint32_t)h3 << 16);
    vl.x = (uint32_t)l0 | ((uint32_t)l1 << 16);
    vl.y = (uint32_t)l2 | ((uint32_t)l3 << 16);
}

__device__ __forceinline__ void pack2_hl(float x, float y,
                                         uint32_t& h, uint32_t& l) {
    uint16_t hx, lx, hy, ly;
    split_bf16(x, hx, lx);
    split_bf16(y, hy, ly);
    h = (uint32_t)hx | ((uint32_t)hy << 16);
    l = (uint32_t)lx | ((uint32_t)ly << 16);
}

// ===========================================================================
// RoPE table init
// ===========================================================================
__global__ void rope_init(const int* __restrict__ tp) {
    int i = blockIdx.x * blockDim.x + threadIdx.x;
    int p = i >> 11;
    int s = i & (SEQL - 1);
    float theta = 1.f / powf(10000.f, (2.f * p) * (1.f / 64.f));
    float ang = (float)tp[s] * theta;
    float sn, cs;
    sincosf(ang, &sn, &cs);
    g_rcos[i] = cs;
    g_rsin[i] = sn;
}

// ===========================================================================
// HMMA split-bf16 GEMM.  mode 0: QKV + RoPE, writes pre-split bf16 hi/lo.
// mode 3: plain fp32 row-major write (output projection).
// ===========================================================================
#define BK 32
#define NCHUNK (D_MODEL / BK)
#define RSB 80
#define TILE_B (128 * RSB)
#define BUF_B (4 * TILE_B)
#define GEMM_SMEM (2 * BUF_B)

__global__ __launch_bounds__(256, 1) void gemm_tc(
    const float* __restrict__ A,
    const float* __restrict__ W0, const float* __restrict__ W1,
    const float* __restrict__ W2,
    float* __restrict__ Dout, int mode)
{
    extern __shared__ char smem[];
    uint32_t sb = smem_to_u32(smem);
    int tid = threadIdx.x;
    int wid = tid >> 5, lane = tid & 31;
    int m0 = blockIdx.y * 128;
    int n0 = blockIdx.x * 128;

    const float* W;
    int nw, mat = 0;
    if (mode == 3) { W = W0; nw = n0; }
    else {
        mat = n0 >> 10;
        nw = n0 & 1023;
        W = (mat == 0) ? W0 : (mat == 1) ? W1 : W2;
    }
    const float* Ap = A + (size_t)m0 * D_MODEL;
    const float* Wp = W + (size_t)nw * D_MODEL;

    int r0 = tid >> 3;
    int kq = tid & 7;

    float4 sa[4], sw[4];

    auto LDG = [&](int c) {
#pragma unroll
        for (int l = 0; l < 4; l++) {
            int r = r0 + 32 * l;
            sa[l] = *reinterpret_cast<const float4*>(
                Ap + (size_t)r * D_MODEL + c * BK + kq * 4);
            sw[l] = *reinterpret_cast<const float4*>(
                Wp + (size_t)r * D_MODEL + c * BK + kq * 4);
        }
    };

    auto STS = [&](int buf) {
        char* base = smem + buf * BUF_B;
#pragma unroll
        for (int l = 0; l < 4; l++) {
            int r = r0 + 32 * l;
            int off = r * RSB + kq * 8;
            uint2 vh, vl;
            split4(sa[l], vh, vl);
            *reinterpret_cast<uint2*>(base + off) = vh;
            *reinterpret_cast<uint2*>(base + TILE_B + off) = vl;
            split4(sw[l], vh, vl);
            *reinterpret_cast<uint2*>(base + 2 * TILE_B + off) = vh;
            *reinterpret_cast<uint2*>(base + 3 * TILE_B + off) = vl;
        }
    };

    float acc[4][4][4];
#pragma unroll
    for (int i = 0; i < 4; i++)
#pragma unroll
        for (int j = 0; j < 4; j++)
#pragma unroll
            for (int k = 0; k < 4; k++) acc[i][j][k] = 0.f;

    int wm = (wid >> 2) * 64;
    int wn = (wid & 3) * 32;

    int a_row = (lane & 7) + ((lane >> 3) & 1) * 8;
    int a_kof = (lane >> 4) * 16;
    int b_row = lane & 7;
    int b_kof = ((lane >> 3) & 1) * 16;

    LDG(0); STS(0);
    __syncthreads();

    for (int c = 0; c < NCHUNK; c++) {
        if (c + 1 < NCHUNK) LDG(c + 1);

        uint32_t bufb = sb + (c & 1) * BUF_B;
#pragma unroll
        for (int kk = 0; kk < 2; kk++) {
            int kb = kk * 32;
            uint32_t ahi[4][4], alo[4][4];
#pragma unroll
            for (int mt = 0; mt < 4; mt++) {
                uint32_t ao = bufb + (wm + mt * 16 + a_row) * RSB + kb + a_kof;
                ldm_x4(ahi[mt], ao);
                ldm_x4(alo[mt], ao + TILE_B);
            }
            uint32_t bhi[4][2], blo[4][2];
#pragma unroll
            for (int nt = 0; nt < 4; nt++) {
                uint32_t bo = bufb + 2 * TILE_B +
                              (wn + nt * 8 + b_row) * RSB + kb + b_kof;
                ldm_x2(bhi[nt], bo);
                ldm_x2(blo[nt], bo + TILE_B);
            }
#pragma unroll
            for (int mt = 0; mt < 4; mt++)
#pragma unroll
                for (int nt = 0; nt < 4; nt++) {
                    mma_bf16(acc[mt][nt], ahi[mt], bhi[nt]);
                    mma_bf16(acc[mt][nt], ahi[mt], blo[nt]);
                    mma_bf16(acc[mt][nt], alo[mt], bhi[nt]);
                }
        }
        if (c + 1 < NCHUNK) STS((c + 1) & 1);
        __syncthreads();
    }

    int er = lane >> 2;
    int ec = (lane & 3) * 2;

    if (mode == 3) {
#pragma unroll
        for (int mt = 0; mt < 4; mt++) {
            int m = m0 + wm + mt * 16 + er;
#pragma unroll
            for (int nt = 0; nt < 4; nt++) {
                int col = n0 + wn + nt * 8 + ec;
                float2 v0 = make_float2(acc[mt][nt][0], acc[mt][nt][1]);
                float2 v1 = make_float2(acc[mt][nt][2], acc[mt][nt][3]);
                *reinterpret_cast<float2*>(Dout + (size_t)m * D_MODEL + col) = v0;
                *reinterpret_cast<float2*>(Dout + (size_t)(m + 8) * D_MODEL + col) = v1;
            }
        }
        return;
    }

    // QKV epilogue: RoPE then split to bf16 hi/lo, write [bh][s][d]
    __nv_bfloat16* Dh = (mat == 0) ? g_qh : (mat == 1) ? g_kh : g_vh;
    __nv_bfloat16* Dl = (mat == 0) ? g_ql : (mat == 1) ? g_kl : g_vl;
#pragma unroll
    for (int mt = 0; mt < 4; mt++) {
        int m = m0 + wm + mt * 16 + er;
        int bi = m >> 11;
        int s0 = m & (SEQL - 1);
#pragma unroll
        for (int nt = 0; nt < 4; nt++) {
            int col = nw + wn + nt * 8 + ec;
            int h = col >> 6, d = col & 63;
            int p = d >> 1;
#pragma unroll
            for (int rr = 0; rr < 2; rr++) {
                int s = s0 + rr * 8;
                float e0 = acc[mt][nt][rr * 2];
                float e1 = acc[mt][nt][rr * 2 + 1];
                float v0, v1;
                if (mat != 2) {
                    float cs = g_rcos[p * SEQL + s];
                    float sn = g_rsin[p * SEQL + s];
                    v0 = e0 * cs - e1 * sn;
                    v1 = e0 * sn + e1 * cs;
                } else {
                    v0 = e0; v1 = e1;
                }
                uint32_t ph, pl;
                pack2_hl(v0, v1, ph, pl);
                size_t o = (((size_t)(bi * NH + h)) * SEQL + s) * HD + d;
                *reinterpret_cast<uint32_t*>(Dh + o) = ph;
                *reinterpret_cast<uint32_t*>(Dl + o) = pl;
            }
        }
    }
}

// ===========================================================================
// HMMA flash attention on pre-split bf16, cp.async double-buffered K/V.
// CTA: 128 q-rows, 8 warps (16 rows each). K/V tiles: 64 keys.
// Smem row stride 144 B (conflict-free ldmatrix).
// ===========================================================================
#define ARS 144
#define AQH_O 0
#define AQL_O (128 * ARS)                       // 18432
#define ASTG(st) (2 * 128 * ARS + (st) * 4 * 64 * ARS)
#define AKH_O(st) (ASTG(st))
#define AKL_O(st) (ASTG(st) + 64 * ARS)
#define AVH_O(st) (ASTG(st) + 2 * 64 * ARS)
#define AVL_O(st) (ASTG(st) + 3 * 64 * ARS)
#define ATTN_SMEM (2 * 128 * ARS + 2 * 4 * 64 * ARS)   // 110592

#define SC2 0.180336880f   /* (1/8) * log2(e) */

__global__ __launch_bounds__(256, 2) void attn_tc()
{
    extern __shared__ char sm[];
    uint32_t sb = smem_to_u32(sm);
    int tid = threadIdx.x;
    int lane = tid & 31, w = tid >> 5;
    int bh = blockIdx.y;
    int qti = gridDim.x - 1 - blockIdx.x;   // long tiles first
    int qm0 = qti * 128;

    size_t base = (size_t)bh * SEQL * HD;

    // ---- Q tile via cp.async (2 regions x 128 rows x 8 chunks of 16B) ----
    {
        const __nv_bfloat16* q_src[2] = { g_qh + base + (size_t)qm0 * HD,
                                          g_ql + base + (size_t)qm0 * HD };
        uint32_t q_dst[2] = { sb + AQH_O, sb + AQL_O };
#pragma unroll
        for (int l = 0; l < 8; l++) {
            int idx = tid + l * 256;         // 0..2047
            int reg = idx >> 10;
            int c = idx & 1023;
            int row = c >> 3, ch = c & 7;
            CP_ASYNC16(q_dst[reg] + row * ARS + ch * 16,
                       q_src[reg] + row * HD + ch * 8);
        }
        CP_COMMIT();
    }

    const __nv_bfloat16* kv_src[4] = { g_kh + base, g_kl + base,
                                       g_vh + base, g_vl + base };

    auto kv_prefetch = [&](int kt) {
        int st = kt & 1;
        uint32_t kv_dst[4] = { sb + AKH_O(st), sb + AKL_O(st),
                               sb + AVH_O(st), sb + AVL_O(st) };
#pragma unroll
        for (int l = 0; l < 8; l++) {
            int idx = tid + l * 256;         // 0..2047
            int reg = idx >> 9;              // 0..3
            int c = idx & 511;
            int row = c >> 3, ch = c & 7;
            CP_ASYNC16(kv_dst[reg] + row * ARS + ch * 16,
                       kv_src[reg] + ((size_t)kt * 64 + row) * HD + ch * 8);
        }
        CP_COMMIT();
    };

    int nkt = 2 * qti + 2;
    kv_prefetch(0);

    float o[8][4];
#pragma unroll
    for (int i = 0; i < 8; i++)
#pragma unroll
        for (int j = 0; j < 4; j++) o[i][j] = 0.f;
    float m0 = -1e30f, m1 = -1e30f, l0 = 0.f, l1 = 0.f;

    int er = lane >> 2;
    int ec2 = (lane & 3) * 2;
    int row_g0 = qm0 + w * 16 + er;
    int row_g1 = row_g0 + 8;

    uint32_t a_addr = sb + AQH_O +
                      (w * 16 + (lane & 15)) * ARS + (lane >> 4) * 16;
    uint32_t kb_row = ((lane >> 4) & 1) * 8 + (lane & 7);
    uint32_t kb_kof = ((lane >> 3) & 1) * 16;
    uint32_t v_key = (lane & 7) + ((lane >> 3) & 1) * 8;
    uint32_t v_dof = ((lane >> 4) & 1) * 16;

    for (int kt = 0; kt < nkt; kt++) {
        if (kt + 1 < nkt) {
            kv_prefetch(kt + 1);
            CP_WAIT(1);
        } else {
            CP_WAIT(0);
        }
        __syncthreads();

        int st = kt & 1;
        uint32_t khb = sb + AKH_O(st);
        uint32_t vhb = sb + AVH_O(st);

        // ---- S = Q K^T (16 x 64 per warp), 3-pass split-bf16 ----
        float sc[8][4];
#pragma unroll
        for (int i = 0; i < 8; i++)
#pragma unroll
            for (int j = 0; j < 4; j++) sc[i][j] = 0.f;

#pragma unroll
        for (int kk = 0; kk < 4; kk++) {
            uint32_t qh[4], ql[4];
            ldm_x4(qh, a_addr + kk * 32);
            ldm_x4(ql, a_addr + kk * 32 + (AQL_O - AQH_O));
#pragma unroll
            for (int ntp = 0; ntp < 4; ntp++) {
                uint32_t bh4[4], bl4[4];
                uint32_t ka = khb + (ntp * 16 + kb_row) * ARS + kk * 32 + kb_kof;
                ldm_x4(bh4, ka);
                ldm_x4(bl4, ka + 64 * ARS);
                mma_bf16(sc[2 * ntp],     qh, bh4);
                mma_bf16(sc[2 * ntp],     qh, bl4);
                mma_bf16(sc[2 * ntp],     ql, bh4);
                mma_bf16(sc[2 * ntp + 1], qh, bh4 + 2);
                mma_bf16(sc[2 * ntp + 1], qh, bl4 + 2);
                mma_bf16(sc[2 * ntp + 1], ql, bh4 + 2);
            }
        }

        // ---- scale + causal mask (log2 domain) ----
        bool diag = (kt >= 2 * qti);
#pragma unroll
        for (int nt = 0; nt < 8; nt++) {
            int c0 = kt * 64 + nt * 8 + ec2;
            if (diag) {
                sc[nt][0] = (c0     > row_g0) ? -1e30f : sc[nt][0] * SC2;
                sc[nt][1] = (c0 + 1 > row_g0) ? -1e30f : sc[nt][1] * SC2;
                sc[nt][2] = (c0     > row_g1) ? -1e30f : sc[nt][2] * SC2;
                sc[nt][3] = (c0 + 1 > row_g1) ? -1e30f : sc[nt][3] * SC2;
            } else {
                sc[nt][0] *= SC2; sc[nt][1] *= SC2;
                sc[nt][2] *= SC2; sc[nt][3] *= SC2;
            }
        }

        // ---- online softmax ----
        float tm0 = -1e30f, tm1 = -1e30f;
#pragma unroll
        for (int nt = 0; nt < 8; nt++) {
            tm0 = fmaxf(tm0, fmaxf(sc[nt][0], sc[nt][1]));
            tm1 = fmaxf(tm1, fmaxf(sc[nt][2], sc[nt][3]));
        }
        tm0 = fmaxf(tm0, __shfl_xor_sync(0xffffffffu, tm0, 1));
        tm0 = fmaxf(tm0, __shfl_xor_sync(0xffffffffu, tm0, 2));
        tm1 = fmaxf(tm1, __shfl_xor_sync(0xffffffffu, tm1, 1));
        tm1 = fmaxf(tm1, __shfl_xor_sync(0xffffffffu, tm1, 2));
        float mn0 = fmaxf(m0, tm0), mn1 = fmaxf(m1, tm1);
        float cf0 = ex2f(m0 - mn0), cf1 = ex2f(m1 - mn1);
        m0 = mn0; m1 = mn1;

        float rs0 = 0.f, rs1 = 0.f;
#pragma unroll
        for (int nt = 0; nt < 8; nt++) {
            float p0 = ex2f(sc[nt][0] - mn0);
            float p1 = ex2f(sc[nt][1] - mn0);
            float p2 = ex2f(sc[nt][2] - mn1);
            float p3 = ex2f(sc[nt][3] - mn1);
            sc[nt][0] = p0; sc[nt][1] = p1; sc[nt][2] = p2; sc[nt][3] = p3;
            rs0 += p0 + p1;
            rs1 += p2 + p3;
        }
        rs0 += __shfl_xor_sync(0xffffffffu, rs0, 1);
        rs0 += __shfl_xor_sync(0xffffffffu, rs0, 2);
        rs1 += __shfl_xor_sync(0xffffffffu, rs1, 1);
        rs1 += __shfl_xor_sync(0xffffffffu, rs1, 2);
        l0 = l0 * cf0 + rs0;
        l1 = l1 * cf1 + rs1;
#pragma unroll
        for (int ng = 0; ng < 8; ng++) {
            o[ng][0] *= cf0; o[ng][1] *= cf0;
            o[ng][2] *= cf1; o[ng][3] *= cf1;
        }

        // ---- O += P V  (3-pass split-bf16, P repacked in-register) ----
#pragma unroll
        for (int kk = 0; kk < 4; kk++) {
            uint32_t ph[4], pl[4];
            pack2_hl(sc[2 * kk][0],     sc[2 * kk][1],     ph[0], pl[0]);
            pack2_hl(sc[2 * kk][2],     sc[2 * kk][3],     ph[1], pl[1]);
            pack2_hl(sc[2 * kk + 1][0], sc[2 * kk + 1][1], ph[2], pl[2]);
            pack2_hl(sc[2 * kk + 1][2], sc[2 * kk + 1][3], ph[3], pl[3]);
#pragma unroll
            for (int ngp = 0; ngp < 4; ngp++) {
                uint32_t vh4[4], vl4[4];
                uint32_t va = vhb + (kk * 16 + v_key) * ARS + ngp * 32 + v_dof;
                ldm_x4_t(vh4, va);
                ldm_x4_t(vl4, va + 64 * ARS);
                mma_bf16(o[2 * ngp],     ph, vh4);
                mma_bf16(o[2 * ngp],     ph, vl4);
                mma_bf16(o[2 * ngp],     pl, vh4);
                mma_bf16(o[2 * ngp + 1], ph, vh4 + 2);
                mma_bf16(o[2 * ngp + 1], ph, vl4 + 2);
                mma_bf16(o[2 * ngp + 1], pl, vh4 + 2);
            }
        }
        __syncthreads();
    }

    // ---- write O/l to g_attn [b, s, h*64+d] ----
    int bi = bh >> 4, h = bh & 15;
    float inv0 = 1.f / l0, inv1 = 1.f / l1;
    int s0 = qm0 + w * 16 + er;
#pragma unroll
    for (int ng = 0; ng < 8; ng++) {
        int d = h * 64 + ng * 8 + ec2;
        float2 v0 = make_float2(o[ng][0] * inv0, o[ng][1] * inv0);
        float2 v1 = make_float2(o[ng][2] * inv1, o[ng][3] * inv1);
        *reinterpret_cast<float2*>(
            g_attn + ((size_t)bi * SEQL + s0) * D_MODEL + d) = v0;
        *reinterpret_cast<float2*>(
            g_attn + ((size_t)bi * SEQL + s0 + 8) * D_MODEL + d) = v1;
    }
}

// ---------------------------------------------------------------------------
extern "C" void kernel_launch(void* const* d_in, const int* in_sizes, int n_in,
                              void* d_out, int out_size)
{
    const float* x  = (const float*)d_in[0];
    const int*   tp = (const int*)d_in[1];
    const float* wq = (const float*)d_in[2];
    const float* wk = (const float*)d_in[3];
    const float* wv = (const float*)d_in[4];
    const float* wo = (const float*)d_in[5];
    float* out = (float*)d_out;

    float* ag;
    cudaGetSymbolAddress((void**)&ag, g_attn);

    cudaFuncSetAttribute(gemm_tc,
                         cudaFuncAttributeMaxDynamicSharedMemorySize,
                         GEMM_SMEM);
    cudaFuncSetAttribute(attn_tc,
                         cudaFuncAttributeMaxDynamicSharedMemorySize,
                         ATTN_SMEM);

    // RoPE cos/sin table
    rope_init<<<(32 * SEQL) / 256, 256>>>(tp);

    // fused QKV projection (N = 3072 stacked) + RoPE + bf16 split epilogue
    dim3 gqkv(3 * D_MODEL / 128, MTOT / 128);
    gemm_tc<<<gqkv, 256, GEMM_SMEM>>>(x, wq, wk, wv, nullptr, 0);

    // causal flash attention (HMMA, cp.async pipelined)
    dim3 gattn(SEQL / 128, BATCH * NH);
    attn_tc<<<gattn, 256, ATTN_SMEM>>>();

    // output projection
    dim3 gproj(D_MODEL / 128, MTOT / 128);
    gemm_tc<<<gproj, 256, GEMM_SMEM>>>(ag, wo, nullptr, nullptr, out, 3);
}

// round 6
// speedup vs baseline: 2.6702x; 1.0038x over previous
#include <cuda_runtime.h>
#include <cuda_bf16.h>
#include <math.h>
#include <cstdint>

#define D_MODEL 1024
#define NH 16
#define HD 64
#define SEQL 2048
#define BATCH 4
#define MTOT (BATCH * SEQL)

// Scratch (static device globals — allocation-free per harness rules)
// Q/K/V stored pre-split as bf16 hi/lo, layout [bh][s][64]
#define QKV_ELEMS ((size_t)BATCH * NH * SEQL * HD)
__device__ __nv_bfloat16 g_qh[QKV_ELEMS], g_ql[QKV_ELEMS];
__device__ __nv_bfloat16 g_kh[QKV_ELEMS], g_kl[QKV_ELEMS];
__device__ __nv_bfloat16 g_vh[QKV_ELEMS], g_vl[QKV_ELEMS];
__device__ float g_attn[(size_t)MTOT * D_MODEL];
__device__ float g_rcos[32 * SEQL];   // [p][s]
__device__ float g_rsin[32 * SEQL];

// ===========================================================================
// helpers
// ===========================================================================
__device__ __forceinline__ uint32_t smem_to_u32(const void* p) {
    uint32_t a;
    asm("{ .reg .u64 t; cvta.to.shared.u64 t, %1; cvt.u32.u64 %0, t; }"
        : "=r"(a) : "l"(p));
    return a;
}

__device__ __forceinline__ void ldm_x4(uint32_t* r, uint32_t addr) {
    asm volatile("ldmatrix.sync.aligned.m8n8.x4.shared.b16 {%0,%1,%2,%3}, [%4];"
                 : "=r"(r[0]), "=r"(r[1]), "=r"(r[2]), "=r"(r[3]) : "r"(addr));
}
__device__ __forceinline__ void ldm_x4_t(uint32_t* r, uint32_t addr) {
    asm volatile("ldmatrix.sync.aligned.m8n8.x4.trans.shared.b16 {%0,%1,%2,%3}, [%4];"
                 : "=r"(r[0]), "=r"(r[1]), "=r"(r[2]), "=r"(r[3]) : "r"(addr));
}
__device__ __forceinline__ void ldm_x2(uint32_t* r, uint32_t addr) {
    asm volatile("ldmatrix.sync.aligned.m8n8.x2.shared.b16 {%0,%1}, [%2];"
                 : "=r"(r[0]), "=r"(r[1]) : "r"(addr));
}

__device__ __forceinline__ void mma_bf16(float* c, const uint32_t* a,
                                         const uint32_t* b) {
    asm volatile(
        "mma.sync.aligned.m16n8k16.row.col.f32.bf16.bf16.f32 "
        "{%0,%1,%2,%3}, {%4,%5,%6,%7}, {%8,%9}, {%0,%1,%2,%3};"
        : "+f"(c[0]), "+f"(c[1]), "+f"(c[2]), "+f"(c[3])
        : "r"(a[0]), "r"(a[1]), "r"(a[2]), "r"(a[3]), "r"(b[0]), "r"(b[1]));
}

__device__ __forceinline__ float ex2f(float x) {
    float y;
    asm("ex2.approx.f32 %0, %1;" : "=f"(y) : "f"(x));
    return y;
}

#define CP_ASYNC16(dst, src) \
    asm volatile("cp.async.cg.shared.global [%0], [%1], 16;" \
                 :: "r"(dst), "l"(src) : "memory")
#define CP_COMMIT() asm volatile("cp.async.commit_group;" ::: "memory")
#define CP_WAIT(n)  asm volatile("cp.async.wait_group %0;" :: "n"(n) : "memory")

// split fp32 -> (hi, lo) bf16 pair
__device__ __forceinline__ void split_bf16(float x, uint16_t& hi, uint16_t& lo) {
    __nv_bfloat16 h = __float2bfloat16_rn(x);
    float hf = __bfloat162float(h);
    __nv_bfloat16 l = __float2bfloat16_rn(x - hf);
    hi = __bfloat16_as_ushort(h);
    lo = __bfloat16_as_ushort(l);
}

__device__ __forceinline__ void split4(const float4& v, uint2& vh, uint2& vl) {
    uint16_t h0, h1, h2, h3, l0, l1, l2, l3;
    split_bf16(v.x, h0, l0); split_bf16(v.y, h1, l1);
    split_bf16(v.z, h2, l2); split_bf16(v.w, h3, l3);
    vh.x = (uint32_t)h0 | ((uint32_t)h1 << 16);
    vh.y = (uint32_t)h2 | ((uint32_t)h3 << 16);
    vl.x = (uint32_t)l0 | ((uint32_t)l1 << 16);
    vl.y = (uint32_t)l2 | ((uint32_t)l3 << 16);
}

__device__ __forceinline__ void pack2_hl(float x, float y,
                                         uint32_t& h, uint32_t& l) {
    uint16_t hx, lx, hy, ly;
    split_bf16(x, hx, lx);
    split_bf16(y, hy, ly);
    h = (uint32_t)hx | ((uint32_t)hy << 16);
    l = (uint32_t)lx | ((uint32_t)ly << 16);
}

// ===========================================================================
// RoPE table init
// ===========================================================================
__global__ void rope_init(const int* __restrict__ tp) {
    int i = blockIdx.x * blockDim.x + threadIdx.x;
    int p = i >> 11;
    int s = i & (SEQL - 1);
    float theta = 1.f / powf(10000.f, (2.f * p) * (1.f / 64.f));
    float ang = (float)tp[s] * theta;
    float sn, cs;
    sincosf(ang, &sn, &cs);
    g_rcos[i] = cs;
    g_rsin[i] = sn;
}

// ===========================================================================
// HMMA split-bf16 GEMM (unchanged).  mode 0: QKV + RoPE -> bf16 hi/lo.
// mode 3: plain fp32 row-major write (output projection).
// ===========================================================================
#define BK 32
#define NCHUNK (D_MODEL / BK)
#define RSB 80
#define TILE_B (128 * RSB)
#define BUF_B (4 * TILE_B)
#define GEMM_SMEM (2 * BUF_B)

__global__ __launch_bounds__(256, 1) void gemm_tc(
    const float* __restrict__ A,
    const float* __restrict__ W0, const float* __restrict__ W1,
    const float* __restrict__ W2,
    float* __restrict__ Dout, int mode)
{
    extern __shared__ char smem[];
    uint32_t sb = smem_to_u32(smem);
    int tid = threadIdx.x;
    int wid = tid >> 5, lane = tid & 31;
    int m0 = blockIdx.y * 128;
    int n0 = blockIdx.x * 128;

    const float* W;
    int nw, mat = 0;
    if (mode == 3) { W = W0; nw = n0; }
    else {
        mat = n0 >> 10;
        nw = n0 & 1023;
        W = (mat == 0) ? W0 : (mat == 1) ? W1 : W2;
    }
    const float* Ap = A + (size_t)m0 * D_MODEL;
    const float* Wp = W + (size_t)nw * D_MODEL;

    int r0 = tid >> 3;
    int kq = tid & 7;

    float4 sa[4], sw[4];

    auto LDG = [&](int c) {
#pragma unroll
        for (int l = 0; l < 4; l++) {
            int r = r0 + 32 * l;
            sa[l] = *reinterpret_cast<const float4*>(
                Ap + (size_t)r * D_MODEL + c * BK + kq * 4);
            sw[l] = *reinterpret_cast<const float4*>(
                Wp + (size_t)r * D_MODEL + c * BK + kq * 4);
        }
    };

    auto STS = [&](int buf) {
        char* base = smem + buf * BUF_B;
#pragma unroll
        for (int l = 0; l < 4; l++) {
            int r = r0 + 32 * l;
            int off = r * RSB + kq * 8;
            uint2 vh, vl;
            split4(sa[l], vh, vl);
            *reinterpret_cast<uint2*>(base + off) = vh;
            *reinterpret_cast<uint2*>(base + TILE_B + off) = vl;
            split4(sw[l], vh, vl);
            *reinterpret_cast<uint2*>(base + 2 * TILE_B + off) = vh;
            *reinterpret_cast<uint2*>(base + 3 * TILE_B + off) = vl;
        }
    };

    float acc[4][4][4];
#pragma unroll
    for (int i = 0; i < 4; i++)
#pragma unroll
        for (int j = 0; j < 4; j++)
#pragma unroll
            for (int k = 0; k < 4; k++) acc[i][j][k] = 0.f;

    int wm = (wid >> 2) * 64;
    int wn = (wid & 3) * 32;

    int a_row = (lane & 7) + ((lane >> 3) & 1) * 8;
    int a_kof = (lane >> 4) * 16;
    int b_row = lane & 7;
    int b_kof = ((lane >> 3) & 1) * 16;

    LDG(0); STS(0);
    __syncthreads();

    for (int c = 0; c < NCHUNK; c++) {
        if (c + 1 < NCHUNK) LDG(c + 1);

        uint32_t bufb = sb + (c & 1) * BUF_B;
#pragma unroll
        for (int kk = 0; kk < 2; kk++) {
            int kb = kk * 32;
            uint32_t ahi[4][4], alo[4][4];
#pragma unroll
            for (int mt = 0; mt < 4; mt++) {
                uint32_t ao = bufb + (wm + mt * 16 + a_row) * RSB + kb + a_kof;
                ldm_x4(ahi[mt], ao);
                ldm_x4(alo[mt], ao + TILE_B);
            }
            uint32_t bhi[4][2], blo[4][2];
#pragma unroll
            for (int nt = 0; nt < 4; nt++) {
                uint32_t bo = bufb + 2 * TILE_B +
                              (wn + nt * 8 + b_row) * RSB + kb + b_kof;
                ldm_x2(bhi[nt], bo);
                ldm_x2(blo[nt], bo + TILE_B);
            }
#pragma unroll
            for (int mt = 0; mt < 4; mt++)
#pragma unroll
                for (int nt = 0; nt < 4; nt++) {
                    mma_bf16(acc[mt][nt], ahi[mt], bhi[nt]);
                    mma_bf16(acc[mt][nt], ahi[mt], blo[nt]);
                    mma_bf16(acc[mt][nt], alo[mt], bhi[nt]);
                }
        }
        if (c + 1 < NCHUNK) STS((c + 1) & 1);
        __syncthreads();
    }

    int er = lane >> 2;
    int ec = (lane & 3) * 2;

    if (mode == 3) {
#pragma unroll
        for (int mt = 0; mt < 4; mt++) {
            int m = m0 + wm + mt * 16 + er;
#pragma unroll
            for (int nt = 0; nt < 4; nt++) {
                int col = n0 + wn + nt * 8 + ec;
                float2 v0 = make_float2(acc[mt][nt][0], acc[mt][nt][1]);
                float2 v1 = make_float2(acc[mt][nt][2], acc[mt][nt][3]);
                *reinterpret_cast<float2*>(Dout + (size_t)m * D_MODEL + col) = v0;
                *reinterpret_cast<float2*>(Dout + (size_t)(m + 8) * D_MODEL + col) = v1;
            }
        }
        return;
    }

    // QKV epilogue: RoPE then split to bf16 hi/lo, write [bh][s][d]
    __nv_bfloat16* Dh = (mat == 0) ? g_qh : (mat == 1) ? g_kh : g_vh;
    __nv_bfloat16* Dl = (mat == 0) ? g_ql : (mat == 1) ? g_kl : g_vl;
#pragma unroll
    for (int mt = 0; mt < 4; mt++) {
        int m = m0 + wm + mt * 16 + er;
        int bi = m >> 11;
        int s0 = m & (SEQL - 1);
#pragma unroll
        for (int nt = 0; nt < 4; nt++) {
            int col = nw + wn + nt * 8 + ec;
            int h = col >> 6, d = col & 63;
            int p = d >> 1;
#pragma unroll
            for (int rr = 0; rr < 2; rr++) {
                int s = s0 + rr * 8;
                float e0 = acc[mt][nt][rr * 2];
                float e1 = acc[mt][nt][rr * 2 + 1];
                float v0, v1;
                if (mat != 2) {
                    float cs = g_rcos[p * SEQL + s];
                    float sn = g_rsin[p * SEQL + s];
                    v0 = e0 * cs - e1 * sn;
                    v1 = e0 * sn + e1 * cs;
                } else {
                    v0 = e0; v1 = e1;
                }
                uint32_t ph, pl;
                pack2_hl(v0, v1, ph, pl);
                size_t o = (((size_t)(bi * NH + h)) * SEQL + s) * HD + d;
                *reinterpret_cast<uint32_t*>(Dh + o) = ph;
                *reinterpret_cast<uint32_t*>(Dl + o) = pl;
            }
        }
    }
}

// ===========================================================================
// HMMA flash attention on pre-split bf16, cp.async double-buffered K/V.
// CTA: 128 q-rows, 8 warps (16 rows each). K/V tiles: 64 keys.
// __launch_bounds__(256,1): avoid register spills (live state > 128 regs).
// Q fragments hoisted into registers once (invariant across K tiles).
// ===========================================================================
#define ARS 144
#define AQH_O 0
#define AQL_O (128 * ARS)
#define ASTG(st) (2 * 128 * ARS + (st) * 4 * 64 * ARS)
#define AKH_O(st) (ASTG(st))
#define AKL_O(st) (ASTG(st) + 64 * ARS)
#define AVH_O(st) (ASTG(st) + 2 * 64 * ARS)
#define AVL_O(st) (ASTG(st) + 3 * 64 * ARS)
#define ATTN_SMEM (2 * 128 * ARS + 2 * 4 * 64 * ARS)   // 110592

#define SC2 0.180336880f   /* (1/8) * log2(e) */

__global__ __launch_bounds__(256, 1) void attn_tc()
{
    extern __shared__ char sm[];
    uint32_t sb = smem_to_u32(sm);
    int tid = threadIdx.x;
    int lane = tid & 31, w = tid >> 5;
    int bh = blockIdx.y;
    int qti = gridDim.x - 1 - blockIdx.x;   // long tiles first
    int qm0 = qti * 128;

    size_t base = (size_t)bh * SEQL * HD;

    // ---- Q tile via cp.async ----
    {
        const __nv_bfloat16* q_src[2] = { g_qh + base + (size_t)qm0 * HD,
                                          g_ql + base + (size_t)qm0 * HD };
        uint32_t q_dst[2] = { sb + AQH_O, sb + AQL_O };
#pragma unroll
        for (int l = 0; l < 8; l++) {
            int idx = tid + l * 256;
            int reg = idx >> 10;
            int c = idx & 1023;
            int row = c >> 3, ch = c & 7;
            CP_ASYNC16(q_dst[reg] + row * ARS + ch * 16,
                       q_src[reg] + row * HD + ch * 8);
        }
        CP_COMMIT();
    }

    const __nv_bfloat16* kv_src[4] = { g_kh + base, g_kl + base,
                                       g_vh + base, g_vl + base };

    auto kv_prefetch = [&](int kt) {
        int st = kt & 1;
        uint32_t kv_dst[4] = { sb + AKH_O(st), sb + AKL_O(st),
                               sb + AVH_O(st), sb + AVL_O(st) };
#pragma unroll
        for (int l = 0; l < 8; l++) {
            int idx = tid + l * 256;
            int reg = idx >> 9;
            int c = idx & 511;
            int row = c >> 3, ch = c & 7;
            CP_ASYNC16(kv_dst[reg] + row * ARS + ch * 16,
                       kv_src[reg] + ((size_t)kt * 64 + row) * HD + ch * 8);
        }
        CP_COMMIT();
    };

    int nkt = 2 * qti + 2;
    kv_prefetch(0);

    // ---- hoist Q fragments to registers (invariant over K loop) ----
    uint32_t qfh[4][4], qfl[4][4];
    {
        CP_WAIT(1);          // Q group done (kv(0) may still be in flight)
        __syncthreads();
        uint32_t a_addr = sb + AQH_O +
                          (w * 16 + (lane & 15)) * ARS + (lane >> 4) * 16;
#pragma unroll
        for (int kk = 0; kk < 4; kk++) {
            ldm_x4(qfh[kk], a_addr + kk * 32);
            ldm_x4(qfl[kk], a_addr + kk * 32 + (AQL_O - AQH_O));
        }
    }

    float o[8][4];
#pragma unroll
    for (int i = 0; i < 8; i++)
#pragma unroll
        for (int j = 0; j < 4; j++) o[i][j] = 0.f;
    float m0 = -1e30f, m1 = -1e30f, l0 = 0.f, l1 = 0.f;

    int er = lane >> 2;
    int ec2 = (lane & 3) * 2;
    int row_g0 = qm0 + w * 16 + er;
    int row_g1 = row_g0 + 8;

    uint32_t kb_row = ((lane >> 4) & 1) * 8 + (lane & 7);
    uint32_t kb_kof = ((lane >> 3) & 1) * 16;
    uint32_t v_key = (lane & 7) + ((lane >> 3) & 1) * 8;
    uint32_t v_dof = ((lane >> 4) & 1) * 16;

    for (int kt = 0; kt < nkt; kt++) {
        if (kt + 1 < nkt) {
            kv_prefetch(kt + 1);
            CP_WAIT(1);
        } else {
            CP_WAIT(0);
        }
        __syncthreads();

        int st = kt & 1;
        uint32_t khb = sb + AKH_O(st);
        uint32_t vhb = sb + AVH_O(st);

        // ---- S = Q K^T (16 x 64 per warp), 3-pass split-bf16 ----
        float sc[8][4];
#pragma unroll
        for (int i = 0; i < 8; i++)
#pragma unroll
            for (int j = 0; j < 4; j++) sc[i][j] = 0.f;

#pragma unroll
        for (int kk = 0; kk < 4; kk++) {
#pragma unroll
            for (int ntp = 0; ntp < 4; ntp++) {
                uint32_t bh4[4], bl4[4];
                uint32_t ka = khb + (ntp * 16 + kb_row) * ARS + kk * 32 + kb_kof;
                ldm_x4(bh4, ka);
                ldm_x4(bl4, ka + 64 * ARS);
                mma_bf16(sc[2 * ntp],     qfh[kk], bh4);
                mma_bf16(sc[2 * ntp],     qfh[kk], bl4);
                mma_bf16(sc[2 * ntp],     qfl[kk], bh4);
                mma_bf16(sc[2 * ntp + 1], qfh[kk], bh4 + 2);
                mma_bf16(sc[2 * ntp + 1], qfh[kk], bl4 + 2);
                mma_bf16(sc[2 * ntp + 1], qfl[kk], bh4 + 2);
            }
        }

        // ---- scale + causal mask (log2 domain) ----
        bool diag = (kt >= 2 * qti);
#pragma unroll
        for (int nt = 0; nt < 8; nt++) {
            int c0 = kt * 64 + nt * 8 + ec2;
            if (diag) {
                sc[nt][0] = (c0     > row_g0) ? -1e30f : sc[nt][0] * SC2;
                sc[nt][1] = (c0 + 1 > row_g0) ? -1e30f : sc[nt][1] * SC2;
                sc[nt][2] = (c0     > row_g1) ? -1e30f : sc[nt][2] * SC2;
                sc[nt][3] = (c0 + 1 > row_g1) ? -1e30f : sc[nt][3] * SC2;
            } else {
                sc[nt][0] *= SC2; sc[nt][1] *= SC2;
                sc[nt][2] *= SC2; sc[nt][3] *= SC2;
            }
        }

        // ---- online softmax ----
        float tm0 = -1e30f, tm1 = -1e30f;
#pragma unroll
        for (int nt = 0; nt < 8; nt++) {
            tm0 = fmaxf(tm0, fmaxf(sc[nt][0], sc[nt][1]));
            tm1 = fmaxf(tm1, fmaxf(sc[nt][2], sc[nt][3]));
        }
        tm0 = fmaxf(tm0, __shfl_xor_sync(0xffffffffu, tm0, 1));
        tm0 = fmaxf(tm0, __shfl_xor_sync(0xffffffffu, tm0, 2));
        tm1 = fmaxf(tm1, __shfl_xor_sync(0xffffffffu, tm1, 1));
        tm1 = fmaxf(tm1, __shfl_xor_sync(0xffffffffu, tm1, 2));
        float mn0 = fmaxf(m0, tm0), mn1 = fmaxf(m1, tm1);
        float cf0 = ex2f(m0 - mn0), cf1 = ex2f(m1 - mn1);
        m0 = mn0; m1 = mn1;

        float rs0 = 0.f, rs1 = 0.f;
#pragma unroll
        for (int nt = 0; nt < 8; nt++) {
            float p0 = ex2f(sc[nt][0] - mn0);
            float p1 = ex2f(sc[nt][1] - mn0);
            float p2 = ex2f(sc[nt][2] - mn1);
            float p3 = ex2f(sc[nt][3] - mn1);
            sc[nt][0] = p0; sc[nt][1] = p1; sc[nt][2] = p2; sc[nt][3] = p3;
            rs0 += p0 + p1;
            rs1 += p2 + p3;
        }
        rs0 += __shfl_xor_sync(0xffffffffu, rs0, 1);
        rs0 += __shfl_xor_sync(0xffffffffu, rs0, 2);
        rs1 += __shfl_xor_sync(0xffffffffu, rs1, 1);
        rs1 += __shfl_xor_sync(0xffffffffu, rs1, 2);
        l0 = l0 * cf0 + rs0;
        l1 = l1 * cf1 + rs1;
#pragma unroll
        for (int ng = 0; ng < 8; ng++) {
            o[ng][0] *= cf0; o[ng][1] *= cf0;
            o[ng][2] *= cf1; o[ng][3] *= cf1;
        }

        // ---- O += P V  (3-pass split-bf16, P repacked in-register) ----
#pragma unroll
        for (int kk = 0; kk < 4; kk++) {
            uint32_t ph[4], pl[4];
            pack2_hl(sc[2 * kk][0],     sc[2 * kk][1],     ph[0], pl[0]);
            pack2_hl(sc[2 * kk][2],     sc[2 * kk][3],     ph[1], pl[1]);
            pack2_hl(sc[2 * kk + 1][0], sc[2 * kk + 1][1], ph[2], pl[2]);
            pack2_hl(sc[2 * kk + 1][2], sc[2 * kk + 1][3], ph[3], pl[3]);
#pragma unroll
            for (int ngp = 0; ngp < 4; ngp++) {
                uint32_t vh4[4], vl4[4];
                uint32_t va = vhb + (kk * 16 + v_key) * ARS + ngp * 32 + v_dof;
                ldm_x4_t(vh4, va);
                ldm_x4_t(vl4, va + 64 * ARS);
                mma_bf16(o[2 * ngp],     ph, vh4);
                mma_bf16(o[2 * ngp],     ph, vl4);
                mma_bf16(o[2 * ngp],     pl, vh4);
                mma_bf16(o[2 * ngp + 1], ph, vh4 + 2);
                mma_bf16(o[2 * ngp + 1], ph, vl4 + 2);
                mma_bf16(o[2 * ngp + 1], pl, vh4 + 2);
            }
        }
        __syncthreads();
    }

    // ---- write O/l to g_attn [b, s, h*64+d] ----
    int bi = bh >> 4, h = bh & 15;
    float inv0 = 1.f / l0, inv1 = 1.f / l1;
    int s0 = qm0 + w * 16 + er;
#pragma unroll
    for (int ng = 0; ng < 8; ng++) {
        int d = h * 64 + ng * 8 + ec2;
        float2 v0 = make_float2(o[ng][0] * inv0, o[ng][1] * inv0);
        float2 v1 = make_float2(o[ng][2] * inv1, o[ng][3] * inv1);
        *reinterpret_cast<float2*>(
            g_attn + ((size_t)bi * SEQL + s0) * D_MODEL + d) = v0;
        *reinterpret_cast<float2*>(
            g_attn + ((size_t)bi * SEQL + s0 + 8) * D_MODEL + d) = v1;
    }
}

// ---------------------------------------------------------------------------
extern "C" void kernel_launch(void* const* d_in, const int* in_sizes, int n_in,
                              void* d_out, int out_size)
{
    const float* x  = (const float*)d_in[0];
    const int*   tp = (const int*)d_in[1];
    const float* wq = (const float*)d_in[2];
    const float* wk = (const float*)d_in[3];
    const float* wv = (const float*)d_in[4];
    const float* wo = (const float*)d_in[5];
    float* out = (float*)d_out;

    float* ag;
    cudaGetSymbolAddress((void**)&ag, g_attn);

    cudaFuncSetAttribute(gemm_tc,
                         cudaFuncAttributeMaxDynamicSharedMemorySize,
                         GEMM_SMEM);
    cudaFuncSetAttribute(attn_tc,
                         cudaFuncAttributeMaxDynamicSharedMemorySize,
                         ATTN_SMEM);

    // RoPE cos/sin table
    rope_init<<<(32 * SEQL) / 256, 256>>>(tp);

    // fused QKV projection (N = 3072 stacked) + RoPE + bf16 split epilogue
    dim3 gqkv(3 * D_MODEL / 128, MTOT / 128);
    gemm_tc<<<gqkv, 256, GEMM_SMEM>>>(x, wq, wk, wv, nullptr, 0);

    // causal flash attention (HMMA, cp.async pipelined)
    dim3 gattn(SEQL / 128, BATCH * NH);
    attn_tc<<<gattn, 256, ATTN_SMEM>>>();

    // output projection
    dim3 gproj(D_MODEL / 128, MTOT / 128);
    gemm_tc<<<gproj, 256, GEMM_SMEM>>>(ag, wo, nullptr, nullptr, out, 3);
}